// round 1
// baseline (speedup 1.0000x reference)
#include <cuda_runtime.h>
#include <math.h>

// ---------------- Problem constants (tree is fully regular) ----------------
#define HS 512          // H_SIZE
#define XS 512          // X_SIZE
#define NW 1536         // 3*HS
#define N_NODES 87381
#define INTERNAL 21845  // nodes [0, INTERNAL) are internal, rest are leaves
#define LEAVES (N_NODES - INTERNAL)  // 65536

// S[d] = (4^d - 1)/3 : first node index at depth d
__constant__ int c_dummy; // keep nvcc happy about empty constant usage

// ---------------- Scratch (device globals; no allocation allowed) ----------
__device__ float g_wx[(size_t)N_NODES * NW];     // wr | wh | wz per node (537 MB)
__device__ float g_hsum[16384 * HS];             // child sum, max M = 16384
__device__ float g_tmp[16384 * HS];              // r * h_sum
__device__ float g_hcand[16384 * HS];            // tanh(wh + ...)
__device__ float g_Z[65536 * HS];                // z_e per edge, max 4*M = 65536

__device__ __forceinline__ float sigf(float x) { return 1.0f / (1.0f + expf(-x)); }

// ---------------------------------------------------------------------------
// Generic fp32 GEMM: C[m][n] = sum_k A[m][k] * B[n][k]   (A: MxK, B: NxK, K=512)
// BM=BN=128, BK=16, 256 threads, 8x8 per thread. MODE selects A-source and epilogue.
//   MODE 0: A = x,            B = W_w,  out g_wx[m*1536+n] = v + bias[n]         (N=1536)
//   MODE 1: A = g_hsum,       B = U_r,  g_tmp = sigmoid(wr + v) * hsum           (N=512)
//   MODE 2: A = g_tmp,        B = U_hc, g_hcand = tanh(wh + v)                   (N=512)
//   MODE 3: A = h + cbase*HS, B = U_z,  g_Z = v                                  (N=512)
// ---------------------------------------------------------------------------
template <int MODE>
__global__ __launch_bounds__(256) void gemm_tn(const float* __restrict__ A,
                                               const float* __restrict__ B,
                                               int M,
                                               const float* __restrict__ bias,
                                               int base) {
    constexpr int K = 512;
    const float* Ap = (MODE == 1) ? g_hsum : (MODE == 2) ? g_tmp : A;

    __shared__ float As[16][128];
    __shared__ float Bs[16][128];

    const int bm = blockIdx.y * 128;
    const int bn = blockIdx.x * 128;
    const int tid = threadIdx.x;
    const int trow = (tid >> 4) << 3;   // [0,128) step 8
    const int tcol = (tid & 15) << 3;   // [0,128) step 8

    float acc[8][8];
#pragma unroll
    for (int i = 0; i < 8; i++)
#pragma unroll
        for (int j = 0; j < 8; j++) acc[i][j] = 0.0f;

    for (int k0 = 0; k0 < K; k0 += 16) {
        // load 128x16 tiles of A and B (transposed into [k][row])
#pragma unroll
        for (int it = 0; it < 2; it++) {
            int q  = tid + it * 256;      // [0,512) -> 512 float4 loads per tile
            int r  = q >> 2;              // row [0,128)
            int c4 = (q & 3) << 2;        // k offset {0,4,8,12}
            float4 v = make_float4(0.f, 0.f, 0.f, 0.f);
            int gm = bm + r;
            if (gm < M) v = *(const float4*)(Ap + (size_t)gm * K + k0 + c4);
            As[c4 + 0][r] = v.x; As[c4 + 1][r] = v.y;
            As[c4 + 2][r] = v.z; As[c4 + 3][r] = v.w;
            int gn = bn + r;  // N always a multiple of 128
            float4 w = *(const float4*)(B + (size_t)gn * K + k0 + c4);
            Bs[c4 + 0][r] = w.x; Bs[c4 + 1][r] = w.y;
            Bs[c4 + 2][r] = w.z; Bs[c4 + 3][r] = w.w;
        }
        __syncthreads();

#pragma unroll
        for (int k = 0; k < 16; k++) {
            float a[8], b[8];
            *(float4*)&a[0] = *(const float4*)&As[k][trow];
            *(float4*)&a[4] = *(const float4*)&As[k][trow + 4];
            *(float4*)&b[0] = *(const float4*)&Bs[k][tcol];
            *(float4*)&b[4] = *(const float4*)&Bs[k][tcol + 4];
#pragma unroll
            for (int i = 0; i < 8; i++)
#pragma unroll
                for (int j = 0; j < 8; j++) acc[i][j] += a[i] * b[j];
        }
        __syncthreads();
    }

    // epilogue
#pragma unroll
    for (int i = 0; i < 8; i++) {
        int m = bm + trow + i;
        if (m >= M) break;
#pragma unroll
        for (int j = 0; j < 8; j++) {
            int n = bn + tcol + j;
            float v = acc[i][j];
            if (MODE == 0) {
                g_wx[(size_t)m * NW + n] = v + bias[n];
            } else if (MODE == 1) {
                float wr = g_wx[(size_t)(base + m) * NW + n];
                float rg = sigf(wr + v);
                g_tmp[m * HS + n] = rg * g_hsum[m * HS + n];
            } else if (MODE == 2) {
                float wh = g_wx[(size_t)(base + m) * NW + HS + n];
                g_hcand[m * HS + n] = tanhf(wh + v);
            } else {
                g_Z[(size_t)m * HS + n] = v;
            }
        }
    }
}

// h_leaf = (1 - sigmoid(wz)) * tanh(wh) for leaf nodes
__global__ void leaf_init(float* __restrict__ h) {
    int idx = blockIdx.x * blockDim.x + threadIdx.x;
    if (idx >= LEAVES * HS) return;
    int node = INTERNAL + (idx >> 9);
    int c = idx & (HS - 1);
    float wh = g_wx[(size_t)node * NW + HS + c];
    float wz = g_wx[(size_t)node * NW + 2 * HS + c];
    h[(size_t)node * HS + c] = (1.0f - sigf(wz)) * tanhf(wh);
}

// g_hsum[r][c] = sum of 4 children h
__global__ void child_sum(const float* __restrict__ h, int M, int cbase) {
    int idx = blockIdx.x * blockDim.x + threadIdx.x;
    if (idx >= M * HS) return;
    int r = idx >> 9;
    int c = idx & (HS - 1);
    const float* hc = h + (size_t)(cbase + 4 * r) * HS + c;
    g_hsum[idx] = hc[0] + hc[HS] + hc[2 * HS] + hc[3 * HS];
}

// h[base+r] = sum_j Z_j*h_child_j + (1 - sum_j sigmoid(Z_j + wz)) * h_cand
__global__ void combine(float* __restrict__ h, int M, int base, int cbase) {
    int idx = blockIdx.x * blockDim.x + threadIdx.x;
    if (idx >= M * HS) return;
    int r = idx >> 9;
    int c = idx & (HS - 1);
    float wz = g_wx[(size_t)(base + r) * NW + 2 * HS + c];
    float acc = 0.0f, zss = 0.0f;
#pragma unroll
    for (int j = 0; j < 4; j++) {
        int e = 4 * r + j;
        float zv = g_Z[(size_t)e * HS + c];
        float hv = h[(size_t)(cbase + e) * HS + c];
        acc += zv * hv;
        zss += sigf(zv + wz);
    }
    h[(size_t)(base + r) * HS + c] = acc + (1.0f - zss) * g_hcand[idx];
}

// ---------------------------------------------------------------------------
extern "C" void kernel_launch(void* const* d_in, const int* in_sizes, int n_in,
                              void* d_out, int out_size) {
    const float* x    = (const float*)d_in[0];
    const float* W_w  = (const float*)d_in[1];
    const float* b_w  = (const float*)d_in[2];
    const float* U_r  = (const float*)d_in[3];
    const float* U_hc = (const float*)d_in[4];
    const float* U_z  = (const float*)d_in[5];
    float* h = (float*)d_out;

    // first node index at each depth: S[d] = (4^d - 1)/3
    static const int S[10] = {0, 1, 5, 21, 85, 341, 1365, 5461, 21845, 87381};

    // 1) wx = x @ W_w^T + b_w  for all nodes
    {
        dim3 grid(NW / 128, (N_NODES + 127) / 128);
        gemm_tn<0><<<grid, 256>>>(x, W_w, N_NODES, b_w, 0);
    }

    // 2) leaf init
    leaf_init<<<(LEAVES * HS + 255) / 256, 256>>>(h);

    // 3) level loop (level l processes nodes at depth 8-l)
    for (int l = 1; l <= 8; l++) {
        int d = 8 - l;
        int M = 1 << (2 * d);       // 4^d nodes at this level
        int base = S[d];
        int cbase = S[d + 1];

        child_sum<<<(M * HS + 255) / 256, 256>>>(h, M, cbase);

        dim3 g1(HS / 128, (M + 127) / 128);
        gemm_tn<1><<<g1, 256>>>(nullptr, U_r, M, nullptr, base);   // r-gate -> g_tmp
        gemm_tn<2><<<g1, 256>>>(nullptr, U_hc, M, nullptr, base);  // h_cand

        dim3 g3(HS / 128, (4 * M + 127) / 128);
        gemm_tn<3><<<g3, 256>>>(h + (size_t)cbase * HS, U_z, 4 * M, nullptr, base); // Z per edge

        combine<<<(M * HS + 255) / 256, 256>>>(h, M, base, cbase);
    }
}

// round 8
// speedup vs baseline: 2.1877x; 2.1877x over previous
#include <cuda_runtime.h>
#include <cuda_bf16.h>
#include <math.h>
#include <cstdint>

// ---------------- Problem constants (tree is fully regular) ----------------
#define HS 512
#define NW 1536
#define N_NODES 87381
#define INTERNAL 21845
#define LEAVES (N_NODES - INTERNAL)   // 65536
#define NPAD (N_NODES + 128)

typedef __nv_bfloat16 bf16;

// ---------------- Scratch (device globals; no allocation allowed) ----------
__device__ __align__(256) float g_wx[(size_t)N_NODES * NW];   // wr | wh | wz
__device__ __align__(256) float g_hsum[16384 * HS];
__device__ __align__(256) float g_hcand[16384 * HS];
__device__ __align__(256) float g_Z[(size_t)65536 * HS];

__device__ __align__(256) bf16 g_xhi[(size_t)NPAD * HS];
__device__ __align__(256) bf16 g_xlo[(size_t)NPAD * HS];
__device__ __align__(256) bf16 g_hhi[(size_t)NPAD * HS];
__device__ __align__(256) bf16 g_hlo[(size_t)NPAD * HS];
__device__ __align__(256) bf16 g_hshi[16384 * HS];
__device__ __align__(256) bf16 g_hslo[16384 * HS];
__device__ __align__(256) bf16 g_thi[16384 * HS];
__device__ __align__(256) bf16 g_tlo[16384 * HS];
__device__ __align__(256) bf16 g_wwhi[NW * HS];
__device__ __align__(256) bf16 g_wwlo[NW * HS];
__device__ __align__(256) bf16 g_urhi[HS * HS];
__device__ __align__(256) bf16 g_urlo[HS * HS];
__device__ __align__(256) bf16 g_uchi[HS * HS];
__device__ __align__(256) bf16 g_uclo[HS * HS];
__device__ __align__(256) bf16 g_uzhi[HS * HS];
__device__ __align__(256) bf16 g_uzlo[HS * HS];

__device__ __forceinline__ float sigf(float x) { return 1.0f / (1.0f + expf(-x)); }

__device__ __forceinline__ void mma16816(float* c, const uint32_t* a, const uint32_t* b) {
    asm volatile("mma.sync.aligned.m16n8k16.row.col.f32.bf16.bf16.f32 "
                 "{%0,%1,%2,%3}, {%4,%5,%6,%7}, {%8,%9}, {%0,%1,%2,%3};"
                 : "+f"(c[0]), "+f"(c[1]), "+f"(c[2]), "+f"(c[3])
                 : "r"(a[0]), "r"(a[1]), "r"(a[2]), "r"(a[3]), "r"(b[0]), "r"(b[1]));
}

// ---------------------------------------------------------------------------
// bf16-split GEMM: C[m][n] = sum_k A[m][k]*B[n][k], K=512, fp32 accum.
// C ≈ Ahi·Bhi + Ahi·Blo + Alo·Bhi.  bf16 has fp32 exponent range -> no
// overflow (fp16 overflowed: h grows to ~1e5 over the 8 tree levels).
// Block 128x128, BK=32, 256 thr (8 warps, warp tile 32x64).
// Shared tiles: 128 rows x 80B (64B data + 16B pad). Plain copies + explicit
// per-lane fragment loads per the PTX mma spec.
// ---------------------------------------------------------------------------
#define ROW_B  80
#define TILE_B (128 * ROW_B)   // 10240 B per tile; 4 tiles = 40960 B static smem

template <int MODE>
__global__ __launch_bounds__(256) void mma_gemm(int M, const float* __restrict__ bias,
                                                int base, int arow0) {
    const bf16* Ahi = (MODE == 0) ? g_xhi : (MODE == 1) ? g_hshi
                    : (MODE == 2) ? g_thi : g_hhi;
    const bf16* Alo = (MODE == 0) ? g_xlo : (MODE == 1) ? g_hslo
                    : (MODE == 2) ? g_tlo : g_hlo;
    const bf16* Bhi = (MODE == 0) ? g_wwhi : (MODE == 1) ? g_urhi
                    : (MODE == 2) ? g_uchi : g_uzhi;
    const bf16* Blo = (MODE == 0) ? g_wwlo : (MODE == 1) ? g_urlo
                    : (MODE == 2) ? g_uclo : g_uzlo;

    __shared__ __align__(16) char smem[4 * TILE_B];
    const int tid = threadIdx.x, lane = tid & 31, warp = tid >> 5;
    const int wm = warp & 3, wn = warp >> 2;          // 4x2 warp grid
    const int bm = blockIdx.y * 128, bn = blockIdx.x * 128;
    const int qr  = lane >> 2;                        // fragment row 0..7
    const int qkb = (lane & 3) * 4;                   // fragment k byte offset

    float acc[2][8][4];
#pragma unroll
    for (int i = 0; i < 2; i++)
#pragma unroll
        for (int j = 0; j < 8; j++)
#pragma unroll
            for (int k = 0; k < 4; k++) acc[i][j][k] = 0.0f;

    const bf16* srcs[4] = {Ahi, Alo, Bhi, Blo};

    for (int kb = 0; kb < 16; kb++) {
        __syncthreads();     // previous iteration's reads complete
        // ---- fill 4 tiles (each 128 rows x 32 bf16) ----
#pragma unroll
        for (int t = 0; t < 4; t++) {
            const bf16* src = srcs[t];
            const int row0 = (t < 2) ? (arow0 + bm) : bn;
#pragma unroll
            for (int j = 0; j < 2; j++) {
                int idx = tid + j * 256;              // 0..511
                int r = idx >> 2, c = idx & 3;
                uint4 v = *(const uint4*)(src + (size_t)(row0 + r) * 512 + kb * 32 + c * 8);
                *(uint4*)(smem + t * TILE_B + r * ROW_B + c * 16) = v;
            }
        }
        __syncthreads();

        // ---- compute: 2 k16-steps ----
#pragma unroll
        for (int ks = 0; ks < 2; ks++) {
            const int kbyte = ks * 32 + qkb;
            uint32_t ahi[2][4], alo[2][4];
#pragma unroll
            for (int mi = 0; mi < 2; mi++) {
                const int ra = (wm * 32 + mi * 16 + qr) * ROW_B + kbyte;
                ahi[mi][0] = *(const uint32_t*)(smem + ra);
                ahi[mi][1] = *(const uint32_t*)(smem + ra + 8 * ROW_B);
                ahi[mi][2] = *(const uint32_t*)(smem + ra + 16);
                ahi[mi][3] = *(const uint32_t*)(smem + ra + 8 * ROW_B + 16);
                alo[mi][0] = *(const uint32_t*)(smem + TILE_B + ra);
                alo[mi][1] = *(const uint32_t*)(smem + TILE_B + ra + 8 * ROW_B);
                alo[mi][2] = *(const uint32_t*)(smem + TILE_B + ra + 16);
                alo[mi][3] = *(const uint32_t*)(smem + TILE_B + ra + 8 * ROW_B + 16);
            }
#pragma unroll
            for (int ng = 0; ng < 8; ng++) {
                const int rb = 2 * TILE_B + (wn * 64 + ng * 8 + qr) * ROW_B + kbyte;
                uint32_t bh[2], bl[2];
                bh[0] = *(const uint32_t*)(smem + rb);
                bh[1] = *(const uint32_t*)(smem + rb + 16);
                bl[0] = *(const uint32_t*)(smem + TILE_B + rb);
                bl[1] = *(const uint32_t*)(smem + TILE_B + rb + 16);
#pragma unroll
                for (int mi = 0; mi < 2; mi++) {
                    mma16816(acc[mi][ng], ahi[mi], bh);
                    mma16816(acc[mi][ng], ahi[mi], bl);
                    mma16816(acc[mi][ng], alo[mi], bh);
                }
            }
        }
    }

    // ---------------- epilogue ----------------
#pragma unroll
    for (int mi = 0; mi < 2; mi++) {
#pragma unroll
        for (int hh = 0; hh < 2; hh++) {
            int m = bm + wm * 32 + mi * 16 + qr + hh * 8;
            if (m >= M) continue;
#pragma unroll
            for (int ni = 0; ni < 8; ni++) {
                int col = bn + wn * 64 + ni * 8 + (lane & 3) * 2;
                float v0 = acc[mi][ni][hh * 2 + 0];
                float v1 = acc[mi][ni][hh * 2 + 1];
                if (MODE == 0) {
                    float2 bb = *(const float2*)(bias + col);
                    *(float2*)(g_wx + (size_t)m * NW + col) =
                        make_float2(v0 + bb.x, v1 + bb.y);
                } else if (MODE == 1) {
                    const float2 wr = *(const float2*)(g_wx + (size_t)(base + m) * NW + col);
                    const float2 hs = *(const float2*)(g_hsum + (size_t)m * HS + col);
                    float t0 = sigf(wr.x + v0) * hs.x;
                    float t1 = sigf(wr.y + v1) * hs.y;
                    bf16 h0 = __float2bfloat16_rn(t0), h1 = __float2bfloat16_rn(t1);
                    *(__nv_bfloat162*)(g_thi + (size_t)m * HS + col) = __halves2bfloat162(h0, h1);
                    *(__nv_bfloat162*)(g_tlo + (size_t)m * HS + col) = __halves2bfloat162(
                        __float2bfloat16_rn(t0 - __bfloat162float(h0)),
                        __float2bfloat16_rn(t1 - __bfloat162float(h1)));
                } else if (MODE == 2) {
                    const float2 wh = *(const float2*)(g_wx + (size_t)(base + m) * NW + HS + col);
                    *(float2*)(g_hcand + (size_t)m * HS + col) =
                        make_float2(tanhf(wh.x + v0), tanhf(wh.y + v1));
                } else {
                    *(float2*)(g_Z + (size_t)m * HS + col) = make_float2(v0, v1);
                }
            }
        }
    }
}

// ---------------- elementwise kernels --------------------------------------
// WHICH: 0 -> x, 1 -> W_w, 2 -> U_r, 3 -> U_hc, 4 -> U_z
template <int WHICH>
__global__ void split_f32(const float* __restrict__ in, int n) {
    int i = blockIdx.x * blockDim.x + threadIdx.x;
    if (i >= n) return;
    bf16* hi = (WHICH == 0) ? g_xhi : (WHICH == 1) ? g_wwhi
             : (WHICH == 2) ? g_urhi : (WHICH == 3) ? g_uchi : g_uzhi;
    bf16* lo = (WHICH == 0) ? g_xlo : (WHICH == 1) ? g_wwlo
             : (WHICH == 2) ? g_urlo : (WHICH == 3) ? g_uclo : g_uzlo;
    float v = in[i];
    bf16 h = __float2bfloat16_rn(v);
    hi[i] = h;
    lo[i] = __float2bfloat16_rn(v - __bfloat162float(h));
}

__global__ void leaf_init(float* __restrict__ h) {
    int idx = blockIdx.x * blockDim.x + threadIdx.x;
    if (idx >= LEAVES * HS) return;
    int node = INTERNAL + (idx >> 9);
    int c = idx & (HS - 1);
    float wh = g_wx[(size_t)node * NW + HS + c];
    float wz = g_wx[(size_t)node * NW + 2 * HS + c];
    float v = (1.0f - sigf(wz)) * tanhf(wh);
    h[(size_t)node * HS + c] = v;
    bf16 b = __float2bfloat16_rn(v);
    g_hhi[(size_t)node * HS + c] = b;
    g_hlo[(size_t)node * HS + c] = __float2bfloat16_rn(v - __bfloat162float(b));
}

__global__ void child_sum(const float* __restrict__ h, int M, int cbase) {
    int idx = blockIdx.x * blockDim.x + threadIdx.x;
    if (idx >= M * HS) return;
    int r = idx >> 9;
    int c = idx & (HS - 1);
    const float* hc = h + (size_t)(cbase + 4 * r) * HS + c;
    float v = hc[0] + hc[HS] + hc[2 * HS] + hc[3 * HS];
    g_hsum[idx] = v;
    bf16 b = __float2bfloat16_rn(v);
    g_hshi[idx] = b;
    g_hslo[idx] = __float2bfloat16_rn(v - __bfloat162float(b));
}

__global__ void combine(float* __restrict__ h, int M, int base, int cbase) {
    int idx = blockIdx.x * blockDim.x + threadIdx.x;
    if (idx >= M * HS) return;
    int r = idx >> 9;
    int c = idx & (HS - 1);
    float wz = g_wx[(size_t)(base + r) * NW + 2 * HS + c];
    float acc = 0.0f, zss = 0.0f;
#pragma unroll
    for (int j = 0; j < 4; j++) {
        int e = 4 * r + j;
        float zv = g_Z[(size_t)e * HS + c];
        float hv = h[(size_t)(cbase + e) * HS + c];
        acc += zv * hv;
        zss += sigf(zv + wz);
    }
    float v = acc + (1.0f - zss) * g_hcand[idx];
    h[(size_t)(base + r) * HS + c] = v;
    bf16 b = __float2bfloat16_rn(v);
    g_hhi[(size_t)(base + r) * HS + c] = b;
    g_hlo[(size_t)(base + r) * HS + c] = __float2bfloat16_rn(v - __bfloat162float(b));
}

// ---------------------------------------------------------------------------
extern "C" void kernel_launch(void* const* d_in, const int* in_sizes, int n_in,
                              void* d_out, int out_size) {
    const float* x    = (const float*)d_in[0];
    const float* W_w  = (const float*)d_in[1];
    const float* b_w  = (const float*)d_in[2];
    float* h = (float*)d_out;
    const float* U_r  = (const float*)d_in[3];
    const float* U_hc = (const float*)d_in[4];
    const float* U_z  = (const float*)d_in[5];

    static const int S[10] = {0, 1, 5, 21, 85, 341, 1365, 5461, 21845, 87381};

    // split fp32 inputs into bf16 hi/lo (destinations are device globals)
    split_f32<0><<<(N_NODES * HS + 255) / 256, 256>>>(x, N_NODES * HS);
    split_f32<1><<<(NW * HS + 255) / 256, 256>>>(W_w, NW * HS);
    split_f32<2><<<(HS * HS + 255) / 256, 256>>>(U_r, HS * HS);
    split_f32<3><<<(HS * HS + 255) / 256, 256>>>(U_hc, HS * HS);
    split_f32<4><<<(HS * HS + 255) / 256, 256>>>(U_z, HS * HS);

    // 1) wx = x @ W_w^T + b_w for all nodes
    {
        dim3 grid(NW / 128, (N_NODES + 127) / 128);
        mma_gemm<0><<<grid, 256>>>(N_NODES, b_w, 0, 0);
    }

    // 2) leaf init
    leaf_init<<<(LEAVES * HS + 255) / 256, 256>>>(h);

    // 3) level loop
    for (int l = 1; l <= 8; l++) {
        int d = 8 - l;
        int M = 1 << (2 * d);
        int base = S[d];
        int cbase = S[d + 1];

        child_sum<<<(M * HS + 255) / 256, 256>>>(h, M, cbase);

        dim3 g1(HS / 128, (M + 127) / 128);
        mma_gemm<1><<<g1, 256>>>(M, nullptr, base, 0);
        mma_gemm<2><<<g1, 256>>>(M, nullptr, base, 0);

        dim3 g3(HS / 128, (4 * M + 127) / 128);
        mma_gemm<3><<<g3, 256>>>(4 * M, nullptr, base, cbase);

        combine<<<(M * HS + 255) / 256, 256>>>(h, M, base, cbase);
    }
}

// round 9
// speedup vs baseline: 2.2912x; 1.0473x over previous
#include <cuda_runtime.h>
#include <cuda_bf16.h>
#include <math.h>
#include <cstdint>

// ---------------- Problem constants (tree is fully regular) ----------------
#define HS 512
#define NW 1536
#define N_NODES 87381
#define INTERNAL 21845
#define LEAVES (N_NODES - INTERNAL)   // 65536
#define NPAD (N_NODES + 128)

typedef __nv_bfloat16 bf16;

// ---------------- Scratch (device globals; no allocation allowed) ----------
__device__ __align__(256) float g_wx[(size_t)N_NODES * NW];   // wr | wh | wz
__device__ __align__(256) float g_hsum[16384 * HS];
__device__ __align__(256) float g_hcand[16384 * HS];
__device__ __align__(256) float g_Z[(size_t)65536 * HS];

__device__ __align__(256) bf16 g_xhi[(size_t)NPAD * HS];
__device__ __align__(256) bf16 g_xlo[(size_t)NPAD * HS];
__device__ __align__(256) bf16 g_hhi[(size_t)NPAD * HS];
__device__ __align__(256) bf16 g_hlo[(size_t)NPAD * HS];
__device__ __align__(256) bf16 g_hshi[16384 * HS];
__device__ __align__(256) bf16 g_hslo[16384 * HS];
__device__ __align__(256) bf16 g_thi[16384 * HS];
__device__ __align__(256) bf16 g_tlo[16384 * HS];
__device__ __align__(256) bf16 g_wwhi[NW * HS];
__device__ __align__(256) bf16 g_wwlo[NW * HS];
__device__ __align__(256) bf16 g_urhi[HS * HS];
__device__ __align__(256) bf16 g_urlo[HS * HS];
__device__ __align__(256) bf16 g_uchi[HS * HS];
__device__ __align__(256) bf16 g_uclo[HS * HS];
__device__ __align__(256) bf16 g_uzhi[HS * HS];
__device__ __align__(256) bf16 g_uzlo[HS * HS];

__device__ __forceinline__ float sigf(float x) { return 1.0f / (1.0f + expf(-x)); }

__device__ __forceinline__ void mma16816(float* c, const uint32_t* a, const uint32_t* b) {
    asm volatile("mma.sync.aligned.m16n8k16.row.col.f32.bf16.bf16.f32 "
                 "{%0,%1,%2,%3}, {%4,%5,%6,%7}, {%8,%9}, {%0,%1,%2,%3};"
                 : "+f"(c[0]), "+f"(c[1]), "+f"(c[2]), "+f"(c[3])
                 : "r"(a[0]), "r"(a[1]), "r"(a[2]), "r"(a[3]), "r"(b[0]), "r"(b[1]));
}
__device__ __forceinline__ void ldm_x4(uint32_t* r, uint32_t addr) {
    asm volatile("ldmatrix.sync.aligned.m8n8.x4.shared.b16 {%0,%1,%2,%3}, [%4];"
                 : "=r"(r[0]), "=r"(r[1]), "=r"(r[2]), "=r"(r[3]) : "r"(addr));
}
__device__ __forceinline__ void cp16(uint32_t dst, const void* src) {
    asm volatile("cp.async.cg.shared.global [%0], [%1], 16;" :: "r"(dst), "l"(src));
}
#define CP_COMMIT() asm volatile("cp.async.commit_group;" ::: "memory")
#define CP_WAIT(n)  asm volatile("cp.async.wait_group %0;" :: "n"(n) : "memory")

// ---------------------------------------------------------------------------
// bf16-split GEMM: C[m][n] = sum_k A[m][k]*B[n][k], K=512, fp32 accum.
// C ≈ Ahi·Bhi + Ahi·Blo + Alo·Bhi.
// Block 128x128, BK=32, 256 thr (8 warps, warp tile 32x64).
// cp.async 2-stage double buffer; ldmatrix.x4 fragment loads.
// Tiles: 128 rows x 80B stride (64B data + 16B pad); stride 80 = 16*5 keeps
// ldmatrix rows on distinct 16B segments (r*5 mod 8 is a permutation).
// ---------------------------------------------------------------------------
#define ROW_B   80
#define TILE_B  (128 * ROW_B)     // 10240
#define STAGE_B (4 * TILE_B)      // Ahi|Alo|Bhi|Blo = 40960
#define SMEM_TOTAL (2 * STAGE_B)  // 81920

template <int MODE>
__global__ __launch_bounds__(256) void mma_gemm(int M, const float* __restrict__ bias,
                                                int base, int arow0, int ncol0) {
    const bf16* Ahi = (MODE == 0) ? g_xhi : (MODE == 1) ? g_hshi
                    : (MODE == 2) ? g_thi : g_hhi;
    const bf16* Alo = (MODE == 0) ? g_xlo : (MODE == 1) ? g_hslo
                    : (MODE == 2) ? g_tlo : g_hlo;
    const bf16* Bhi = (MODE == 0) ? g_wwhi : (MODE == 1) ? g_urhi
                    : (MODE == 2) ? g_uchi : g_uzhi;
    const bf16* Blo = (MODE == 0) ? g_wwlo : (MODE == 1) ? g_urlo
                    : (MODE == 2) ? g_uclo : g_uzlo;

    extern __shared__ __align__(16) char smem[];
    const uint32_t sb = (uint32_t)__cvta_generic_to_shared(smem);
    const int tid = threadIdx.x, lane = tid & 31, warp = tid >> 5;
    const int wm = warp & 3, wn = warp >> 2;          // 4x2 warp grid
    const int bm = blockIdx.y * 128, bn = blockIdx.x * 128;
    const int qr = lane >> 2;                         // fragment row 0..7

    // ldmatrix.x4 per-lane source row/col within a 16x32B tile
    const int lrow   = (lane & 7) + ((lane >> 3) & 1) * 8;
    const int lcol16 = ((lane >> 4) & 1) * 16;

    float acc[2][8][4];
#pragma unroll
    for (int i = 0; i < 2; i++)
#pragma unroll
        for (int j = 0; j < 8; j++)
#pragma unroll
            for (int k = 0; k < 4; k++) acc[i][j][k] = 0.0f;

    const bf16* srcs[4] = {Ahi, Alo, Bhi, Blo};

    // fill stage s with k-block kb (4 tiles x 512 16B chunks, 8 per thread)
    auto fill = [&](int s, int kb) {
#pragma unroll
        for (int t = 0; t < 4; t++) {
            const bf16* src = srcs[t];
            const int row0 = (t < 2) ? (arow0 + bm) : (ncol0 + bn);
#pragma unroll
            for (int j = 0; j < 2; j++) {
                int idx = tid + j * 256;              // 0..511
                int r = idx >> 2, c = idx & 3;
                cp16(sb + s * STAGE_B + t * TILE_B + r * ROW_B + c * 16,
                     src + (size_t)(row0 + r) * 512 + kb * 32 + c * 8);
            }
        }
        CP_COMMIT();
    };

    fill(0, 0);

    for (int kb = 0; kb < 16; kb++) {
        if (kb + 1 < 16) { fill((kb + 1) & 1, kb + 1); CP_WAIT(1); }
        else             { CP_WAIT(0); }
        __syncthreads();                              // stage kb visible to all

        const uint32_t st = sb + (kb & 1) * STAGE_B;
#pragma unroll
        for (int ks = 0; ks < 2; ks++) {
            uint32_t ah[2][4], al[2][4], bh[4][4], bl[4][4];
#pragma unroll
            for (int mi = 0; mi < 2; mi++) {
                uint32_t ra = st + (wm * 32 + mi * 16 + lrow) * ROW_B + ks * 32 + lcol16;
                ldm_x4(ah[mi], ra);
                ldm_x4(al[mi], ra + TILE_B);
            }
#pragma unroll
            for (int p = 0; p < 4; p++) {
                uint32_t rb = st + 2 * TILE_B + (wn * 64 + p * 16 + lrow) * ROW_B + ks * 32 + lcol16;
                ldm_x4(bh[p], rb);
                ldm_x4(bl[p], rb + TILE_B);
            }
#pragma unroll
            for (int ng = 0; ng < 8; ng++) {
                const int p = ng >> 1, s1 = ng & 1;
                uint32_t bfh[2] = {bh[p][s1], bh[p][s1 + 2]};
                uint32_t bfl[2] = {bl[p][s1], bl[p][s1 + 2]};
#pragma unroll
                for (int mi = 0; mi < 2; mi++) {
                    mma16816(acc[mi][ng], ah[mi], bfh);
                    mma16816(acc[mi][ng], ah[mi], bfl);
                    mma16816(acc[mi][ng], al[mi], bfh);
                }
            }
        }
        __syncthreads();          // all reads done before buffer reuse
    }

    // ---------------- epilogue ----------------
#pragma unroll
    for (int mi = 0; mi < 2; mi++) {
#pragma unroll
        for (int hh = 0; hh < 2; hh++) {
            int m = bm + wm * 32 + mi * 16 + qr + hh * 8;
            if (m >= M) continue;
#pragma unroll
            for (int ni = 0; ni < 8; ni++) {
                int col = bn + wn * 64 + ni * 8 + (lane & 3) * 2;
                float v0 = acc[mi][ni][hh * 2 + 0];
                float v1 = acc[mi][ni][hh * 2 + 1];
                if (MODE == 0) {
                    float2 bb = *(const float2*)(bias + ncol0 + col);
                    *(float2*)(g_wx + (size_t)(arow0 + m) * NW + ncol0 + col) =
                        make_float2(v0 + bb.x, v1 + bb.y);
                } else if (MODE == 1) {
                    const float2 wr = *(const float2*)(g_wx + (size_t)(base + m) * NW + col);
                    const float2 hs = *(const float2*)(g_hsum + (size_t)m * HS + col);
                    float t0 = sigf(wr.x + v0) * hs.x;
                    float t1 = sigf(wr.y + v1) * hs.y;
                    bf16 h0 = __float2bfloat16_rn(t0), h1 = __float2bfloat16_rn(t1);
                    *(__nv_bfloat162*)(g_thi + (size_t)m * HS + col) = __halves2bfloat162(h0, h1);
                    *(__nv_bfloat162*)(g_tlo + (size_t)m * HS + col) = __halves2bfloat162(
                        __float2bfloat16_rn(t0 - __bfloat162float(h0)),
                        __float2bfloat16_rn(t1 - __bfloat162float(h1)));
                } else if (MODE == 2) {
                    const float2 wh = *(const float2*)(g_wx + (size_t)(base + m) * NW + HS + col);
                    *(float2*)(g_hcand + (size_t)m * HS + col) =
                        make_float2(tanhf(wh.x + v0), tanhf(wh.y + v1));
                } else {
                    *(float2*)(g_Z + (size_t)m * HS + col) = make_float2(v0, v1);
                }
            }
        }
    }
}

// ---------------- elementwise kernels --------------------------------------
// WHICH: 0 -> x, 1 -> W_w, 2 -> U_r, 3 -> U_hc, 4 -> U_z
template <int WHICH>
__global__ void split_f32(const float* __restrict__ in, int n) {
    int i = blockIdx.x * blockDim.x + threadIdx.x;
    if (i >= n) return;
    bf16* hi = (WHICH == 0) ? g_xhi : (WHICH == 1) ? g_wwhi
             : (WHICH == 2) ? g_urhi : (WHICH == 3) ? g_uchi : g_uzhi;
    bf16* lo = (WHICH == 0) ? g_xlo : (WHICH == 1) ? g_wwlo
             : (WHICH == 2) ? g_urlo : (WHICH == 3) ? g_uclo : g_uzlo;
    float v = in[i];
    bf16 h = __float2bfloat16_rn(v);
    hi[i] = h;
    lo[i] = __float2bfloat16_rn(v - __bfloat162float(h));
}

__global__ void leaf_init(float* __restrict__ h) {
    int idx = blockIdx.x * blockDim.x + threadIdx.x;
    if (idx >= LEAVES * HS) return;
    int node = INTERNAL + (idx >> 9);
    int c = idx & (HS - 1);
    float wh = g_wx[(size_t)node * NW + HS + c];
    float wz = g_wx[(size_t)node * NW + 2 * HS + c];
    float v = (1.0f - sigf(wz)) * tanhf(wh);
    h[(size_t)node * HS + c] = v;
    bf16 b = __float2bfloat16_rn(v);
    g_hhi[(size_t)node * HS + c] = b;
    g_hlo[(size_t)node * HS + c] = __float2bfloat16_rn(v - __bfloat162float(b));
}

__global__ void child_sum(const float* __restrict__ h, int M, int cbase) {
    int idx = blockIdx.x * blockDim.x + threadIdx.x;
    if (idx >= M * HS) return;
    int r = idx >> 9;
    int c = idx & (HS - 1);
    const float* hc = h + (size_t)(cbase + 4 * r) * HS + c;
    float v = hc[0] + hc[HS] + hc[2 * HS] + hc[3 * HS];
    g_hsum[idx] = v;
    bf16 b = __float2bfloat16_rn(v);
    g_hshi[idx] = b;
    g_hslo[idx] = __float2bfloat16_rn(v - __bfloat162float(b));
}

__global__ void combine(float* __restrict__ h, int M, int base, int cbase) {
    int idx = blockIdx.x * blockDim.x + threadIdx.x;
    if (idx >= M * HS) return;
    int r = idx >> 9;
    int c = idx & (HS - 1);
    float wz = g_wx[(size_t)(base + r) * NW + 2 * HS + c];
    float acc = 0.0f, zss = 0.0f;
#pragma unroll
    for (int j = 0; j < 4; j++) {
        int e = 4 * r + j;
        float zv = g_Z[(size_t)e * HS + c];
        float hv = h[(size_t)(cbase + e) * HS + c];
        acc += zv * hv;
        zss += sigf(zv + wz);
    }
    float v = acc + (1.0f - zss) * g_hcand[idx];
    h[(size_t)(base + r) * HS + c] = v;
    bf16 b = __float2bfloat16_rn(v);
    g_hhi[(size_t)(base + r) * HS + c] = b;
    g_hlo[(size_t)(base + r) * HS + c] = __float2bfloat16_rn(v - __bfloat162float(b));
}

// ---------------------------------------------------------------------------
extern "C" void kernel_launch(void* const* d_in, const int* in_sizes, int n_in,
                              void* d_out, int out_size) {
    const float* x    = (const float*)d_in[0];
    const float* W_w  = (const float*)d_in[1];
    const float* b_w  = (const float*)d_in[2];
    const float* U_r  = (const float*)d_in[3];
    const float* U_hc = (const float*)d_in[4];
    const float* U_z  = (const float*)d_in[5];
    float* h = (float*)d_out;

    static const int S[10] = {0, 1, 5, 21, 85, 341, 1365, 5461, 21845, 87381};

    cudaFuncSetAttribute(mma_gemm<0>, cudaFuncAttributeMaxDynamicSharedMemorySize, SMEM_TOTAL);
    cudaFuncSetAttribute(mma_gemm<1>, cudaFuncAttributeMaxDynamicSharedMemorySize, SMEM_TOTAL);
    cudaFuncSetAttribute(mma_gemm<2>, cudaFuncAttributeMaxDynamicSharedMemorySize, SMEM_TOTAL);
    cudaFuncSetAttribute(mma_gemm<3>, cudaFuncAttributeMaxDynamicSharedMemorySize, SMEM_TOTAL);

    // split fp32 inputs into bf16 hi/lo (destinations are device globals)
    split_f32<0><<<(N_NODES * HS + 255) / 256, 256>>>(x, N_NODES * HS);
    split_f32<1><<<(NW * HS + 255) / 256, 256>>>(W_w, NW * HS);
    split_f32<2><<<(HS * HS + 255) / 256, 256>>>(U_r, HS * HS);
    split_f32<3><<<(HS * HS + 255) / 256, 256>>>(U_hc, HS * HS);
    split_f32<4><<<(HS * HS + 255) / 256, 256>>>(U_z, HS * HS);

    // 1) wx: internal nodes need wr|wh|wz (1536 cols); leaves only wh|wz (1024)
    {
        dim3 gi(NW / 128, (INTERNAL + 127) / 128);
        mma_gemm<0><<<gi, 256, SMEM_TOTAL>>>(INTERNAL, b_w, 0, 0, 0);
        dim3 gl((NW - HS) / 128, LEAVES / 128);
        mma_gemm<0><<<gl, 256, SMEM_TOTAL>>>(LEAVES, b_w, INTERNAL, INTERNAL, HS);
    }

    // 2) leaf init
    leaf_init<<<(LEAVES * HS + 255) / 256, 256>>>(h);

    // 3) level loop
    for (int l = 1; l <= 8; l++) {
        int d = 8 - l;
        int M = 1 << (2 * d);
        int base = S[d];
        int cbase = S[d + 1];

        child_sum<<<(M * HS + 255) / 256, 256>>>(h, M, cbase);

        dim3 g1(HS / 128, (M + 127) / 128);
        mma_gemm<1><<<g1, 256, SMEM_TOTAL>>>(M, nullptr, base, 0, 0);
        mma_gemm<2><<<g1, 256, SMEM_TOTAL>>>(M, nullptr, base, 0, 0);

        dim3 g3(HS / 128, (4 * M + 127) / 128);
        mma_gemm<3><<<g3, 256, SMEM_TOTAL>>>(4 * M, nullptr, base, cbase, 0);

        combine<<<(M * HS + 255) / 256, 256>>>(h, M, base, cbase);
    }
}

// round 11
// speedup vs baseline: 2.5692x; 1.1214x over previous
#include <cuda_runtime.h>
#include <cuda_bf16.h>
#include <math.h>
#include <cstdint>

// ---------------- Problem constants (tree is fully regular) ----------------
#define HS 512
#define NW 1536
#define N_NODES 87381
#define INTERNAL 21845
#define LEAVES (N_NODES - INTERNAL)   // 65536
#define NPAD (N_NODES + 128)

typedef __nv_bfloat16 bf16;

// ---------------- Scratch (device globals; no allocation allowed) ----------
__device__ __align__(256) float g_wx[(size_t)INTERNAL * NW + 256]; // internal only
__device__ __align__(256) float g_hsum[16384 * HS];
__device__ __align__(256) float g_hcand[16384 * HS];
__device__ __align__(256) float g_Z[(size_t)65536 * HS];

__device__ __align__(256) bf16 g_xhi[(size_t)NPAD * HS];
__device__ __align__(256) bf16 g_xlo[(size_t)NPAD * HS];
__device__ __align__(256) bf16 g_hhi[(size_t)NPAD * HS];
__device__ __align__(256) bf16 g_hlo[(size_t)NPAD * HS];
__device__ __align__(256) bf16 g_hshi[16384 * HS];
__device__ __align__(256) bf16 g_hslo[16384 * HS];
__device__ __align__(256) bf16 g_thi[16384 * HS];
__device__ __align__(256) bf16 g_tlo[16384 * HS];
__device__ __align__(256) bf16 g_wwhi[NW * HS];
__device__ __align__(256) bf16 g_wwlo[NW * HS];
__device__ __align__(256) bf16 g_urhi[HS * HS];
__device__ __align__(256) bf16 g_urlo[HS * HS];
__device__ __align__(256) bf16 g_uchi[HS * HS];
__device__ __align__(256) bf16 g_uclo[HS * HS];
__device__ __align__(256) bf16 g_uzhi[HS * HS];
__device__ __align__(256) bf16 g_uzlo[HS * HS];

__device__ __forceinline__ float sigf(float x) { return 1.0f / (1.0f + expf(-x)); }

__device__ __forceinline__ void mma16816(float* c, const uint32_t* a, const uint32_t* b) {
    asm volatile("mma.sync.aligned.m16n8k16.row.col.f32.bf16.bf16.f32 "
                 "{%0,%1,%2,%3}, {%4,%5,%6,%7}, {%8,%9}, {%0,%1,%2,%3};"
                 : "+f"(c[0]), "+f"(c[1]), "+f"(c[2]), "+f"(c[3])
                 : "r"(a[0]), "r"(a[1]), "r"(a[2]), "r"(a[3]), "r"(b[0]), "r"(b[1]));
}
__device__ __forceinline__ void ldm_x4(uint32_t* r, uint32_t addr) {
    asm volatile("ldmatrix.sync.aligned.m8n8.x4.shared.b16 {%0,%1,%2,%3}, [%4];"
                 : "=r"(r[0]), "=r"(r[1]), "=r"(r[2]), "=r"(r[3]) : "r"(addr));
}
__device__ __forceinline__ void cp16(uint32_t dst, const void* src) {
    asm volatile("cp.async.cg.shared.global [%0], [%1], 16;" :: "r"(dst), "l"(src));
}
#define CP_COMMIT() asm volatile("cp.async.commit_group;" ::: "memory")
#define CP_WAIT(n)  asm volatile("cp.async.wait_group %0;" :: "n"(n) : "memory")

// ---------------------------------------------------------------------------
// bf16-split GEMM: C[m][n] = sum_k A[m][k]*B[n][k], K=512, fp32 accum.
// C ≈ Ahi·Bhi + Ahi·Blo + Alo·Bhi.
// Block 128x128 (MODE<4) or 128x64 dual-output (MODE 4: wh & wz tiles,
// warps 0-3 compute wh, warps 4-7 wz, epilogue fuses leaf h directly).
// cp.async 2-stage double buffer; ldmatrix.x4; 80B-stride conflict-free tiles.
// ---------------------------------------------------------------------------
#define ROW_B   80
#define TILE_B  (128 * ROW_B)     // 10240
#define STAGE_B (4 * TILE_B)      // Ahi|Alo|Bhi|Blo = 40960
#define SMEM_TOTAL (2 * STAGE_B)  // 81920

template <int MODE>
__global__ __launch_bounds__(256) void mma_gemm(int M, const float* __restrict__ bias,
                                                int base, int arow0, int ncol0,
                                                float* __restrict__ hout) {
    const bf16* Ahi = (MODE == 0 || MODE == 4) ? g_xhi : (MODE == 1) ? g_hshi
                    : (MODE == 2) ? g_thi : g_hhi;
    const bf16* Alo = (MODE == 0 || MODE == 4) ? g_xlo : (MODE == 1) ? g_hslo
                    : (MODE == 2) ? g_tlo : g_hlo;
    const bf16* Bhi = (MODE == 0 || MODE == 4) ? g_wwhi : (MODE == 1) ? g_urhi
                    : (MODE == 2) ? g_uchi : g_uzhi;
    const bf16* Blo = (MODE == 0 || MODE == 4) ? g_wwlo : (MODE == 1) ? g_urlo
                    : (MODE == 2) ? g_uclo : g_uzlo;

    extern __shared__ __align__(16) char smem[];
    const uint32_t sb = (uint32_t)__cvta_generic_to_shared(smem);
    const int tid = threadIdx.x, lane = tid & 31, warp = tid >> 5;
    const int wm = warp & 3, wn = warp >> 2;          // 4x2 warp grid
    const int bm = blockIdx.y * 128;
    const int bn = blockIdx.x * 128;
    const int bcol0 = (MODE == 4) ? blockIdx.x * 64 : (ncol0 + bn);
    const int qr = lane >> 2;

    const int lrow   = (lane & 7) + ((lane >> 3) & 1) * 8;
    const int lcol16 = ((lane >> 4) & 1) * 16;

    float acc[2][8][4];
#pragma unroll
    for (int i = 0; i < 2; i++)
#pragma unroll
        for (int j = 0; j < 8; j++)
#pragma unroll
            for (int k = 0; k < 4; k++) acc[i][j][k] = 0.0f;

    const bf16* srcs[4] = {Ahi, Alo, Bhi, Blo};

    auto fill = [&](int s, int kb) {
#pragma unroll
        for (int t = 0; t < 4; t++) {
            const bf16* src = srcs[t];
#pragma unroll
            for (int j = 0; j < 2; j++) {
                int idx = tid + j * 256;              // 0..511
                int r = idx >> 2, c = idx & 3;
                int grow;
                if (t < 2) grow = arow0 + bm + r;
                else if (MODE == 4) grow = HS + ((r >> 6) & 1) * HS + bcol0 + (r & 63);
                else grow = bcol0 + r;
                cp16(sb + s * STAGE_B + t * TILE_B + r * ROW_B + c * 16,
                     src + (size_t)grow * 512 + kb * 32 + c * 8);
            }
        }
        CP_COMMIT();
    };

    fill(0, 0);

    for (int kb = 0; kb < 16; kb++) {
        if (kb + 1 < 16) { fill((kb + 1) & 1, kb + 1); CP_WAIT(1); }
        else             { CP_WAIT(0); }
        __syncthreads();

        const uint32_t st = sb + (kb & 1) * STAGE_B;
#pragma unroll
        for (int ks = 0; ks < 2; ks++) {
            uint32_t ah[2][4], al[2][4], bh[4][4], bl[4][4];
#pragma unroll
            for (int mi = 0; mi < 2; mi++) {
                uint32_t ra = st + (wm * 32 + mi * 16 + lrow) * ROW_B + ks * 32 + lcol16;
                ldm_x4(ah[mi], ra);
                ldm_x4(al[mi], ra + TILE_B);
            }
#pragma unroll
            for (int p = 0; p < 4; p++) {
                uint32_t rb = st + 2 * TILE_B + (wn * 64 + p * 16 + lrow) * ROW_B + ks * 32 + lcol16;
                ldm_x4(bh[p], rb);
                ldm_x4(bl[p], rb + TILE_B);
            }
#pragma unroll
            for (int ng = 0; ng < 8; ng++) {
                const int p = ng >> 1, s1 = ng & 1;
                uint32_t bfh[2] = {bh[p][s1], bh[p][s1 + 2]};
                uint32_t bfl[2] = {bl[p][s1], bl[p][s1 + 2]};
#pragma unroll
                for (int mi = 0; mi < 2; mi++) {
                    mma16816(acc[mi][ng], ah[mi], bfh);
                    mma16816(acc[mi][ng], ah[mi], bfl);
                    mma16816(acc[mi][ng], al[mi], bfh);
                }
            }
        }
        __syncthreads();
    }

    // ---------------- epilogue ----------------
    if (MODE == 4) {
        // warps 4-7 hold wz pre-activations -> smem; warps 0-3 hold wh.
        float* sf = (float*)smem;                      // 128 x 65 floats
#pragma unroll
        for (int mi = 0; mi < 2; mi++)
#pragma unroll
            for (int hh = 0; hh < 2; hh++)
#pragma unroll
                for (int ni = 0; ni < 8; ni++) {
                    if (wn == 1) {
                        int row = wm * 32 + mi * 16 + qr + hh * 8;
                        int colw = ni * 8 + (lane & 3) * 2;
                        sf[row * 65 + colw]     = acc[mi][ni][hh * 2 + 0];
                        sf[row * 65 + colw + 1] = acc[mi][ni][hh * 2 + 1];
                    }
                }
        __syncthreads();
        if (wn == 0) {
#pragma unroll
            for (int mi = 0; mi < 2; mi++)
#pragma unroll
                for (int hh = 0; hh < 2; hh++)
#pragma unroll
                    for (int ni = 0; ni < 8; ni++) {
                        int row = wm * 32 + mi * 16 + qr + hh * 8;
                        int colw = ni * 8 + (lane & 3) * 2;
                        int c = bcol0 + colw;
                        float wh0 = acc[mi][ni][hh * 2 + 0] + bias[HS + c];
                        float wh1 = acc[mi][ni][hh * 2 + 1] + bias[HS + c + 1];
                        float wz0 = sf[row * 65 + colw]     + bias[2 * HS + c];
                        float wz1 = sf[row * 65 + colw + 1] + bias[2 * HS + c + 1];
                        float v0 = (1.0f - sigf(wz0)) * tanhf(wh0);
                        float v1 = (1.0f - sigf(wz1)) * tanhf(wh1);
                        size_t node = (size_t)INTERNAL + bm + row;
                        *(float2*)(hout + node * HS + c) = make_float2(v0, v1);
                        bf16 b0 = __float2bfloat16_rn(v0), b1 = __float2bfloat16_rn(v1);
                        *(__nv_bfloat162*)(g_hhi + node * HS + c) = __halves2bfloat162(b0, b1);
                        *(__nv_bfloat162*)(g_hlo + node * HS + c) = __halves2bfloat162(
                            __float2bfloat16_rn(v0 - __bfloat162float(b0)),
                            __float2bfloat16_rn(v1 - __bfloat162float(b1)));
                    }
        }
        return;
    }

#pragma unroll
    for (int mi = 0; mi < 2; mi++) {
#pragma unroll
        for (int hh = 0; hh < 2; hh++) {
            int m = bm + wm * 32 + mi * 16 + qr + hh * 8;
            if (m >= M) continue;
#pragma unroll
            for (int ni = 0; ni < 8; ni++) {
                int col = bn + wn * 64 + ni * 8 + (lane & 3) * 2;
                float v0 = acc[mi][ni][hh * 2 + 0];
                float v1 = acc[mi][ni][hh * 2 + 1];
                if (MODE == 0) {
                    float2 bb = *(const float2*)(bias + ncol0 + col);
                    *(float2*)(g_wx + (size_t)(arow0 + m) * NW + ncol0 + col) =
                        make_float2(v0 + bb.x, v1 + bb.y);
                } else if (MODE == 1) {
                    const float2 wr = *(const float2*)(g_wx + (size_t)(base + m) * NW + col);
                    const float2 hs = *(const float2*)(g_hsum + (size_t)m * HS + col);
                    float t0 = sigf(wr.x + v0) * hs.x;
                    float t1 = sigf(wr.y + v1) * hs.y;
                    bf16 h0 = __float2bfloat16_rn(t0), h1 = __float2bfloat16_rn(t1);
                    *(__nv_bfloat162*)(g_thi + (size_t)m * HS + col) = __halves2bfloat162(h0, h1);
                    *(__nv_bfloat162*)(g_tlo + (size_t)m * HS + col) = __halves2bfloat162(
                        __float2bfloat16_rn(t0 - __bfloat162float(h0)),
                        __float2bfloat16_rn(t1 - __bfloat162float(h1)));
                } else if (MODE == 2) {
                    const float2 wh = *(const float2*)(g_wx + (size_t)(base + m) * NW + HS + col);
                    *(float2*)(g_hcand + (size_t)m * HS + col) =
                        make_float2(tanhf(wh.x + v0), tanhf(wh.y + v1));
                } else {
                    *(float2*)(g_Z + (size_t)m * HS + col) = make_float2(v0, v1);
                }
            }
        }
    }
}

// ---------------- elementwise kernels (vectorized) --------------------------
// WHICH: 0 -> x, 1 -> W_w, 2 -> U_r, 3 -> U_hc, 4 -> U_z. n8 = elems/8.
template <int WHICH>
__global__ void split_f32(const float* __restrict__ in, int n8) {
    int i = blockIdx.x * blockDim.x + threadIdx.x;
    if (i >= n8) return;
    bf16* hi = (WHICH == 0) ? g_xhi : (WHICH == 1) ? g_wwhi
             : (WHICH == 2) ? g_urhi : (WHICH == 3) ? g_uchi : g_uzhi;
    bf16* lo = (WHICH == 0) ? g_xlo : (WHICH == 1) ? g_wwlo
             : (WHICH == 2) ? g_urlo : (WHICH == 3) ? g_uclo : g_uzlo;
    float4 a = ((const float4*)in)[2 * i];
    float4 b = ((const float4*)in)[2 * i + 1];
    float v[8] = {a.x, a.y, a.z, a.w, b.x, b.y, b.z, b.w};
    __nv_bfloat162 hw[4], lw[4];
#pragma unroll
    for (int j = 0; j < 4; j++) {
        bf16 h0 = __float2bfloat16_rn(v[2 * j]);
        bf16 h1 = __float2bfloat16_rn(v[2 * j + 1]);
        hw[j] = __halves2bfloat162(h0, h1);
        lw[j] = __halves2bfloat162(
            __float2bfloat16_rn(v[2 * j] - __bfloat162float(h0)),
            __float2bfloat16_rn(v[2 * j + 1] - __bfloat162float(h1)));
    }
    ((uint4*)hi)[i] = *(uint4*)hw;
    ((uint4*)lo)[i] = *(uint4*)lw;
}

// n4 = M*HS/4
__global__ void child_sum(const float* __restrict__ h, int n4, int cbase) {
    int idx = blockIdx.x * blockDim.x + threadIdx.x;
    if (idx >= n4) return;
    int r = idx >> 7, c4 = idx & 127;
    const float4* hc = (const float4*)(h + (size_t)(cbase + 4 * r) * HS) + c4;
    float4 s0 = hc[0], s1 = hc[128], s2 = hc[256], s3 = hc[384];
    float4 v = make_float4(s0.x + s1.x + s2.x + s3.x, s0.y + s1.y + s2.y + s3.y,
                           s0.z + s1.z + s2.z + s3.z, s0.w + s1.w + s2.w + s3.w);
    ((float4*)g_hsum)[idx] = v;
    float vv[4] = {v.x, v.y, v.z, v.w};
    __nv_bfloat162 hw[2], lw[2];
#pragma unroll
    for (int j = 0; j < 2; j++) {
        bf16 h0 = __float2bfloat16_rn(vv[2 * j]);
        bf16 h1 = __float2bfloat16_rn(vv[2 * j + 1]);
        hw[j] = __halves2bfloat162(h0, h1);
        lw[j] = __halves2bfloat162(
            __float2bfloat16_rn(vv[2 * j] - __bfloat162float(h0)),
            __float2bfloat16_rn(vv[2 * j + 1] - __bfloat162float(h1)));
    }
    ((uint2*)g_hshi)[idx] = *(uint2*)hw;
    ((uint2*)g_hslo)[idx] = *(uint2*)lw;
}

// n4 = M*HS/4
__global__ void combine(float* __restrict__ h, int n4, int base, int cbase) {
    int idx = blockIdx.x * blockDim.x + threadIdx.x;
    if (idx >= n4) return;
    int r = idx >> 7, c4 = idx & 127;
    float4 wz = *((const float4*)(g_wx + (size_t)(base + r) * NW + 2 * HS) + c4);
    float4 acc = make_float4(0.f, 0.f, 0.f, 0.f);
    float4 zss = make_float4(0.f, 0.f, 0.f, 0.f);
#pragma unroll
    for (int j = 0; j < 4; j++) {
        float4 z  = *((const float4*)(g_Z + (size_t)(4 * r + j) * HS) + c4);
        float4 hv = *((const float4*)(h + (size_t)(cbase + 4 * r + j) * HS) + c4);
        acc.x += z.x * hv.x; acc.y += z.y * hv.y;
        acc.z += z.z * hv.z; acc.w += z.w * hv.w;
        zss.x += sigf(z.x + wz.x); zss.y += sigf(z.y + wz.y);
        zss.z += sigf(z.z + wz.z); zss.w += sigf(z.w + wz.w);
    }
    float4 hc = ((const float4*)g_hcand)[idx];
    float4 v = make_float4(acc.x + (1.f - zss.x) * hc.x, acc.y + (1.f - zss.y) * hc.y,
                           acc.z + (1.f - zss.z) * hc.z, acc.w + (1.f - zss.w) * hc.w);
    *((float4*)(h + (size_t)(base + r) * HS) + c4) = v;
    float vv[4] = {v.x, v.y, v.z, v.w};
    __nv_bfloat162 hw[2], lw[2];
#pragma unroll
    for (int j = 0; j < 2; j++) {
        bf16 h0 = __float2bfloat16_rn(vv[2 * j]);
        bf16 h1 = __float2bfloat16_rn(vv[2 * j + 1]);
        hw[j] = __halves2bfloat162(h0, h1);
        lw[j] = __halves2bfloat162(
            __float2bfloat16_rn(vv[2 * j] - __bfloat162float(h0)),
            __float2bfloat16_rn(vv[2 * j + 1] - __bfloat162float(h1)));
    }
    *((uint2*)(g_hhi + (size_t)(base + r) * HS) + c4) = *(uint2*)hw;
    *((uint2*)(g_hlo + (size_t)(base + r) * HS) + c4) = *(uint2*)lw;
}

// ---------------------------------------------------------------------------
extern "C" void kernel_launch(void* const* d_in, const int* in_sizes, int n_in,
                              void* d_out, int out_size) {
    const float* x    = (const float*)d_in[0];
    const float* W_w  = (const float*)d_in[1];
    const float* b_w  = (const float*)d_in[2];
    const float* U_r  = (const float*)d_in[3];
    const float* U_hc = (const float*)d_in[4];
    const float* U_z  = (const float*)d_in[5];
    float* h = (float*)d_out;

    static const int S[10] = {0, 1, 5, 21, 85, 341, 1365, 5461, 21845, 87381};

    cudaFuncSetAttribute(mma_gemm<0>, cudaFuncAttributeMaxDynamicSharedMemorySize, SMEM_TOTAL);
    cudaFuncSetAttribute(mma_gemm<1>, cudaFuncAttributeMaxDynamicSharedMemorySize, SMEM_TOTAL);
    cudaFuncSetAttribute(mma_gemm<2>, cudaFuncAttributeMaxDynamicSharedMemorySize, SMEM_TOTAL);
    cudaFuncSetAttribute(mma_gemm<3>, cudaFuncAttributeMaxDynamicSharedMemorySize, SMEM_TOTAL);
    cudaFuncSetAttribute(mma_gemm<4>, cudaFuncAttributeMaxDynamicSharedMemorySize, SMEM_TOTAL);

    // split fp32 inputs into bf16 hi/lo (8 elems/thread)
    split_f32<0><<<(N_NODES * HS / 8 + 255) / 256, 256>>>(x, N_NODES * HS / 8);
    split_f32<1><<<(NW * HS / 8 + 255) / 256, 256>>>(W_w, NW * HS / 8);
    split_f32<2><<<(HS * HS / 8 + 255) / 256, 256>>>(U_r, HS * HS / 8);
    split_f32<3><<<(HS * HS / 8 + 255) / 256, 256>>>(U_hc, HS * HS / 8);
    split_f32<4><<<(HS * HS / 8 + 255) / 256, 256>>>(U_z, HS * HS / 8);

    // 1) internal nodes: wx = x @ W_w^T + b_w (all 1536 cols, stored)
    {
        dim3 gi(NW / 128, (INTERNAL + 127) / 128);
        mma_gemm<0><<<gi, 256, SMEM_TOTAL>>>(INTERNAL, b_w, 0, 0, 0, nullptr);
    }
    // 2) leaves: fused GEMM -> h directly (wh & wz tiles per block, no wx)
    {
        dim3 gl(HS / 64, LEAVES / 128);
        mma_gemm<4><<<gl, 256, SMEM_TOTAL>>>(LEAVES, b_w, 0, INTERNAL, 0, h);
    }

    // 3) level loop
    for (int l = 1; l <= 8; l++) {
        int d = 8 - l;
        int M = 1 << (2 * d);
        int base = S[d];
        int cbase = S[d + 1];

        child_sum<<<(M * 128 + 255) / 256, 256>>>(h, M * 128, cbase);

        dim3 g1(HS / 128, (M + 127) / 128);
        mma_gemm<1><<<g1, 256, SMEM_TOTAL>>>(M, nullptr, base, 0, 0, nullptr);
        mma_gemm<2><<<g1, 256, SMEM_TOTAL>>>(M, nullptr, base, 0, 0, nullptr);

        dim3 g3(HS / 128, (4 * M + 127) / 128);
        mma_gemm<3><<<g3, 256, SMEM_TOTAL>>>(4 * M, nullptr, base, cbase, 0, nullptr);

        combine<<<(M * 128 + 255) / 256, 256>>>(h, M * 128, base, cbase);
    }
}

// round 12
// speedup vs baseline: 2.6186x; 1.0192x over previous
#include <cuda_runtime.h>
#include <cuda_bf16.h>
#include <math.h>
#include <cstdint>

// ---------------- Problem constants (tree is fully regular) ----------------
#define HS 512
#define NW 1536
#define N_NODES 87381
#define INTERNAL 21845
#define LEAVES (N_NODES - INTERNAL)   // 65536
#define NPAD (N_NODES + 128)

typedef __nv_bfloat16 bf16;

// ---------------- Scratch (device globals; no allocation allowed) ----------
__device__ __align__(256) float g_wx[(size_t)INTERNAL * NW + 256]; // internal only
__device__ __align__(256) float g_hsum[16384 * HS];
__device__ __align__(256) float g_hcand[16384 * HS];
__device__ __align__(256) float g_Z[(size_t)65536 * HS];

__device__ __align__(256) bf16 g_xhi[(size_t)NPAD * HS];
__device__ __align__(256) bf16 g_xlo[(size_t)NPAD * HS];
__device__ __align__(256) bf16 g_hhi[(size_t)NPAD * HS];
__device__ __align__(256) bf16 g_hlo[(size_t)NPAD * HS];
__device__ __align__(256) bf16 g_hshi[16384 * HS];
__device__ __align__(256) bf16 g_hslo[16384 * HS];
__device__ __align__(256) bf16 g_thi[16384 * HS];
__device__ __align__(256) bf16 g_tlo[16384 * HS];
__device__ __align__(256) bf16 g_wwhi[NW * HS];
__device__ __align__(256) bf16 g_wwlo[NW * HS];
__device__ __align__(256) bf16 g_urhi[HS * HS];
__device__ __align__(256) bf16 g_urlo[HS * HS];
__device__ __align__(256) bf16 g_uchi[HS * HS];
__device__ __align__(256) bf16 g_uclo[HS * HS];
__device__ __align__(256) bf16 g_uzhi[HS * HS];
__device__ __align__(256) bf16 g_uzlo[HS * HS];

__device__ __forceinline__ float sigf(float x) { return 1.0f / (1.0f + expf(-x)); }

__device__ __forceinline__ void mma16816(float* c, const uint32_t* a, const uint32_t* b) {
    asm volatile("mma.sync.aligned.m16n8k16.row.col.f32.bf16.bf16.f32 "
                 "{%0,%1,%2,%3}, {%4,%5,%6,%7}, {%8,%9}, {%0,%1,%2,%3};"
                 : "+f"(c[0]), "+f"(c[1]), "+f"(c[2]), "+f"(c[3])
                 : "r"(a[0]), "r"(a[1]), "r"(a[2]), "r"(a[3]), "r"(b[0]), "r"(b[1]));
}
__device__ __forceinline__ void ldm_x4(uint32_t* r, uint32_t addr) {
    asm volatile("ldmatrix.sync.aligned.m8n8.x4.shared.b16 {%0,%1,%2,%3}, [%4];"
                 : "=r"(r[0]), "=r"(r[1]), "=r"(r[2]), "=r"(r[3]) : "r"(addr));
}
__device__ __forceinline__ void cp16(uint32_t dst, const void* src) {
    asm volatile("cp.async.cg.shared.global [%0], [%1], 16;" :: "r"(dst), "l"(src));
}
#define CP_COMMIT() asm volatile("cp.async.commit_group;" ::: "memory")
#define CP_WAIT(n)  asm volatile("cp.async.wait_group %0;" :: "n"(n) : "memory")

// ---------------------------------------------------------------------------
// bf16-split GEMM: C[m][n] = sum_k A[m][k]*B[n][k], K=512, fp32 accum.
// C ≈ Ahi·Bhi + Ahi·Blo + Alo·Bhi.
// Block 128x128 (MODE<4) or 128x64 dual-output (MODE 4: wh & wz, fused leaf h).
// cp.async 2-stage double buffer, BK=64 (8 k-blocks of 4 k16-steps).
// Tiles: 128 rows x 144B stride (128B data + 16B pad); 144=16*9 -> r*9 mod 8
// is a permutation -> ldmatrix conflict-free.
// ---------------------------------------------------------------------------
#define ROW_B   144
#define TILE_B  (128 * ROW_B)     // 18432
#define STAGE_B (4 * TILE_B)      // 73728
#define SMEM_TOTAL (2 * STAGE_B)  // 147456

template <int MODE>
__global__ __launch_bounds__(256) void mma_gemm(int M, const float* __restrict__ bias,
                                                int base, int arow0, int ncol0,
                                                float* __restrict__ hout) {
    const bf16* Ahi = (MODE == 0 || MODE == 4) ? g_xhi : (MODE == 1) ? g_hshi
                    : (MODE == 2) ? g_thi : g_hhi;
    const bf16* Alo = (MODE == 0 || MODE == 4) ? g_xlo : (MODE == 1) ? g_hslo
                    : (MODE == 2) ? g_tlo : g_hlo;
    const bf16* Bhi = (MODE == 0 || MODE == 4) ? g_wwhi : (MODE == 1) ? g_urhi
                    : (MODE == 2) ? g_uchi : g_uzhi;
    const bf16* Blo = (MODE == 0 || MODE == 4) ? g_wwlo : (MODE == 1) ? g_urlo
                    : (MODE == 2) ? g_uclo : g_uzlo;

    extern __shared__ __align__(16) char smem[];
    const uint32_t sb = (uint32_t)__cvta_generic_to_shared(smem);
    const int tid = threadIdx.x, lane = tid & 31, warp = tid >> 5;
    const int wm = warp & 3, wn = warp >> 2;          // 4x2 warp grid
    const int bm = blockIdx.y * 128;
    const int bn = blockIdx.x * 128;
    const int bcol0 = (MODE == 4) ? blockIdx.x * 64 : (ncol0 + bn);
    const int qr = lane >> 2;

    const int lrow   = (lane & 7) + ((lane >> 3) & 1) * 8;
    const int lcol16 = ((lane >> 4) & 1) * 16;

    float acc[2][8][4];
#pragma unroll
    for (int i = 0; i < 2; i++)
#pragma unroll
        for (int j = 0; j < 8; j++)
#pragma unroll
            for (int k = 0; k < 4; k++) acc[i][j][k] = 0.0f;

    const bf16* srcs[4] = {Ahi, Alo, Bhi, Blo};

    // fill stage s with k-block kb: 4 tiles x 128 rows x 64 bf16 (8 16B chunks/row)
    auto fill = [&](int s, int kb) {
#pragma unroll
        for (int t = 0; t < 4; t++) {
            const bf16* src = srcs[t];
#pragma unroll
            for (int j = 0; j < 4; j++) {
                int idx = tid + j * 256;              // 0..1023
                int r = idx >> 3, c = idx & 7;
                int grow;
                if (t < 2) grow = arow0 + bm + r;
                else if (MODE == 4) grow = HS + ((r >> 6) & 1) * HS + bcol0 + (r & 63);
                else grow = bcol0 + r;
                cp16(sb + s * STAGE_B + t * TILE_B + r * ROW_B + c * 16,
                     src + (size_t)grow * 512 + kb * 64 + c * 8);
            }
        }
        CP_COMMIT();
    };

    fill(0, 0);

    for (int kb = 0; kb < 8; kb++) {
        if (kb + 1 < 8) { fill((kb + 1) & 1, kb + 1); CP_WAIT(1); }
        else            { CP_WAIT(0); }
        __syncthreads();

        const uint32_t st = sb + (kb & 1) * STAGE_B;
#pragma unroll
        for (int ks = 0; ks < 4; ks++) {
            uint32_t ah[2][4], al[2][4], bh[4][4], bl[4][4];
#pragma unroll
            for (int mi = 0; mi < 2; mi++) {
                uint32_t ra = st + (wm * 32 + mi * 16 + lrow) * ROW_B + ks * 32 + lcol16;
                ldm_x4(ah[mi], ra);
                ldm_x4(al[mi], ra + TILE_B);
            }
#pragma unroll
            for (int p = 0; p < 4; p++) {
                uint32_t rb = st + 2 * TILE_B + (wn * 64 + p * 16 + lrow) * ROW_B + ks * 32 + lcol16;
                ldm_x4(bh[p], rb);
                ldm_x4(bl[p], rb + TILE_B);
            }
#pragma unroll
            for (int ng = 0; ng < 8; ng++) {
                const int p = ng >> 1, s1 = ng & 1;
                uint32_t bfh[2] = {bh[p][s1], bh[p][s1 + 2]};
                uint32_t bfl[2] = {bl[p][s1], bl[p][s1 + 2]};
#pragma unroll
                for (int mi = 0; mi < 2; mi++) {
                    mma16816(acc[mi][ng], ah[mi], bfh);
                    mma16816(acc[mi][ng], ah[mi], bfl);
                    mma16816(acc[mi][ng], al[mi], bfh);
                }
            }
        }
        __syncthreads();
    }

    // ---------------- epilogue ----------------
    if (MODE == 4) {
        float* sf = (float*)smem;                      // 128 x 65 floats
#pragma unroll
        for (int mi = 0; mi < 2; mi++)
#pragma unroll
            for (int hh = 0; hh < 2; hh++)
#pragma unroll
                for (int ni = 0; ni < 8; ni++) {
                    if (wn == 1) {
                        int row = wm * 32 + mi * 16 + qr + hh * 8;
                        int colw = ni * 8 + (lane & 3) * 2;
                        sf[row * 65 + colw]     = acc[mi][ni][hh * 2 + 0];
                        sf[row * 65 + colw + 1] = acc[mi][ni][hh * 2 + 1];
                    }
                }
        __syncthreads();
        if (wn == 0) {
#pragma unroll
            for (int mi = 0; mi < 2; mi++)
#pragma unroll
                for (int hh = 0; hh < 2; hh++)
#pragma unroll
                    for (int ni = 0; ni < 8; ni++) {
                        int row = wm * 32 + mi * 16 + qr + hh * 8;
                        int colw = ni * 8 + (lane & 3) * 2;
                        int c = bcol0 + colw;
                        float wh0 = acc[mi][ni][hh * 2 + 0] + bias[HS + c];
                        float wh1 = acc[mi][ni][hh * 2 + 1] + bias[HS + c + 1];
                        float wz0 = sf[row * 65 + colw]     + bias[2 * HS + c];
                        float wz1 = sf[row * 65 + colw + 1] + bias[2 * HS + c + 1];
                        float v0 = (1.0f - sigf(wz0)) * tanhf(wh0);
                        float v1 = (1.0f - sigf(wz1)) * tanhf(wh1);
                        size_t node = (size_t)INTERNAL + bm + row;
                        *(float2*)(hout + node * HS + c) = make_float2(v0, v1);
                        bf16 b0 = __float2bfloat16_rn(v0), b1 = __float2bfloat16_rn(v1);
                        *(__nv_bfloat162*)(g_hhi + node * HS + c) = __halves2bfloat162(b0, b1);
                        *(__nv_bfloat162*)(g_hlo + node * HS + c) = __halves2bfloat162(
                            __float2bfloat16_rn(v0 - __bfloat162float(b0)),
                            __float2bfloat16_rn(v1 - __bfloat162float(b1)));
                    }
        }
        return;
    }

#pragma unroll
    for (int mi = 0; mi < 2; mi++) {
#pragma unroll
        for (int hh = 0; hh < 2; hh++) {
            int m = bm + wm * 32 + mi * 16 + qr + hh * 8;
            if (m >= M) continue;
#pragma unroll
            for (int ni = 0; ni < 8; ni++) {
                int col = bn + wn * 64 + ni * 8 + (lane & 3) * 2;
                float v0 = acc[mi][ni][hh * 2 + 0];
                float v1 = acc[mi][ni][hh * 2 + 1];
                if (MODE == 0) {
                    float2 bb = *(const float2*)(bias + ncol0 + col);
                    *(float2*)(g_wx + (size_t)(arow0 + m) * NW + ncol0 + col) =
                        make_float2(v0 + bb.x, v1 + bb.y);
                } else if (MODE == 1) {
                    const float2 wr = *(const float2*)(g_wx + (size_t)(base + m) * NW + col);
                    const float2 hs = *(const float2*)(g_hsum + (size_t)m * HS + col);
                    float t0 = sigf(wr.x + v0) * hs.x;
                    float t1 = sigf(wr.y + v1) * hs.y;
                    bf16 h0 = __float2bfloat16_rn(t0), h1 = __float2bfloat16_rn(t1);
                    *(__nv_bfloat162*)(g_thi + (size_t)m * HS + col) = __halves2bfloat162(h0, h1);
                    *(__nv_bfloat162*)(g_tlo + (size_t)m * HS + col) = __halves2bfloat162(
                        __float2bfloat16_rn(t0 - __bfloat162float(h0)),
                        __float2bfloat16_rn(t1 - __bfloat162float(h1)));
                } else if (MODE == 2) {
                    const float2 wh = *(const float2*)(g_wx + (size_t)(base + m) * NW + HS + col);
                    *(float2*)(g_hcand + (size_t)m * HS + col) =
                        make_float2(tanhf(wh.x + v0), tanhf(wh.y + v1));
                } else {
                    *(float2*)(g_Z + (size_t)m * HS + col) = make_float2(v0, v1);
                }
            }
        }
    }
}

// ---------------- elementwise kernels (vectorized) --------------------------
template <int WHICH>
__global__ void split_f32(const float* __restrict__ in, int n8) {
    int i = blockIdx.x * blockDim.x + threadIdx.x;
    if (i >= n8) return;
    bf16* hi = (WHICH == 0) ? g_xhi : (WHICH == 1) ? g_wwhi
             : (WHICH == 2) ? g_urhi : (WHICH == 3) ? g_uchi : g_uzhi;
    bf16* lo = (WHICH == 0) ? g_xlo : (WHICH == 1) ? g_wwlo
             : (WHICH == 2) ? g_urlo : (WHICH == 3) ? g_uclo : g_uzlo;
    float4 a = ((const float4*)in)[2 * i];
    float4 b = ((const float4*)in)[2 * i + 1];
    float v[8] = {a.x, a.y, a.z, a.w, b.x, b.y, b.z, b.w};
    __nv_bfloat162 hw[4], lw[4];
#pragma unroll
    for (int j = 0; j < 4; j++) {
        bf16 h0 = __float2bfloat16_rn(v[2 * j]);
        bf16 h1 = __float2bfloat16_rn(v[2 * j + 1]);
        hw[j] = __halves2bfloat162(h0, h1);
        lw[j] = __halves2bfloat162(
            __float2bfloat16_rn(v[2 * j] - __bfloat162float(h0)),
            __float2bfloat16_rn(v[2 * j + 1] - __bfloat162float(h1)));
    }
    ((uint4*)hi)[i] = *(uint4*)hw;
    ((uint4*)lo)[i] = *(uint4*)lw;
}

__global__ void child_sum(const float* __restrict__ h, int n4, int cbase) {
    int idx = blockIdx.x * blockDim.x + threadIdx.x;
    if (idx >= n4) return;
    int r = idx >> 7, c4 = idx & 127;
    const float4* hc = (const float4*)(h + (size_t)(cbase + 4 * r) * HS) + c4;
    float4 s0 = hc[0], s1 = hc[128], s2 = hc[256], s3 = hc[384];
    float4 v = make_float4(s0.x + s1.x + s2.x + s3.x, s0.y + s1.y + s2.y + s3.y,
                           s0.z + s1.z + s2.z + s3.z, s0.w + s1.w + s2.w + s3.w);
    ((float4*)g_hsum)[idx] = v;
    float vv[4] = {v.x, v.y, v.z, v.w};
    __nv_bfloat162 hw[2], lw[2];
#pragma unroll
    for (int j = 0; j < 2; j++) {
        bf16 h0 = __float2bfloat16_rn(vv[2 * j]);
        bf16 h1 = __float2bfloat16_rn(vv[2 * j + 1]);
        hw[j] = __halves2bfloat162(h0, h1);
        lw[j] = __halves2bfloat162(
            __float2bfloat16_rn(vv[2 * j] - __bfloat162float(h0)),
            __float2bfloat16_rn(vv[2 * j + 1] - __bfloat162float(h1)));
    }
    ((uint2*)g_hshi)[idx] = *(uint2*)hw;
    ((uint2*)g_hslo)[idx] = *(uint2*)lw;
}

__global__ void combine(float* __restrict__ h, int n4, int base, int cbase) {
    int idx = blockIdx.x * blockDim.x + threadIdx.x;
    if (idx >= n4) return;
    int r = idx >> 7, c4 = idx & 127;
    float4 wz = *((const float4*)(g_wx + (size_t)(base + r) * NW + 2 * HS) + c4);
    float4 acc = make_float4(0.f, 0.f, 0.f, 0.f);
    float4 zss = make_float4(0.f, 0.f, 0.f, 0.f);
#pragma unroll
    for (int j = 0; j < 4; j++) {
        float4 z  = *((const float4*)(g_Z + (size_t)(4 * r + j) * HS) + c4);
        float4 hv = *((const float4*)(h + (size_t)(cbase + 4 * r + j) * HS) + c4);
        acc.x += z.x * hv.x; acc.y += z.y * hv.y;
        acc.z += z.z * hv.z; acc.w += z.w * hv.w;
        zss.x += sigf(z.x + wz.x); zss.y += sigf(z.y + wz.y);
        zss.z += sigf(z.z + wz.z); zss.w += sigf(z.w + wz.w);
    }
    float4 hc = ((const float4*)g_hcand)[idx];
    float4 v = make_float4(acc.x + (1.f - zss.x) * hc.x, acc.y + (1.f - zss.y) * hc.y,
                           acc.z + (1.f - zss.z) * hc.z, acc.w + (1.f - zss.w) * hc.w);
    *((float4*)(h + (size_t)(base + r) * HS) + c4) = v;
    float vv[4] = {v.x, v.y, v.z, v.w};
    __nv_bfloat162 hw[2], lw[2];
#pragma unroll
    for (int j = 0; j < 2; j++) {
        bf16 h0 = __float2bfloat16_rn(vv[2 * j]);
        bf16 h1 = __float2bfloat16_rn(vv[2 * j + 1]);
        hw[j] = __halves2bfloat162(h0, h1);
        lw[j] = __halves2bfloat162(
            __float2bfloat16_rn(vv[2 * j] - __bfloat162float(h0)),
            __float2bfloat16_rn(vv[2 * j + 1] - __bfloat162float(h1)));
    }
    *((uint2*)(g_hhi + (size_t)(base + r) * HS) + c4) = *(uint2*)hw;
    *((uint2*)(g_hlo + (size_t)(base + r) * HS) + c4) = *(uint2*)lw;
}

// ---------------------------------------------------------------------------
extern "C" void kernel_launch(void* const* d_in, const int* in_sizes, int n_in,
                              void* d_out, int out_size) {
    const float* x    = (const float*)d_in[0];
    const float* W_w  = (const float*)d_in[1];
    const float* b_w  = (const float*)d_in[2];
    const float* U_r  = (const float*)d_in[3];
    const float* U_hc = (const float*)d_in[4];
    const float* U_z  = (const float*)d_in[5];
    float* h = (float*)d_out;

    static const int S[10] = {0, 1, 5, 21, 85, 341, 1365, 5461, 21845, 87381};

    cudaFuncSetAttribute(mma_gemm<0>, cudaFuncAttributeMaxDynamicSharedMemorySize, SMEM_TOTAL);
    cudaFuncSetAttribute(mma_gemm<1>, cudaFuncAttributeMaxDynamicSharedMemorySize, SMEM_TOTAL);
    cudaFuncSetAttribute(mma_gemm<2>, cudaFuncAttributeMaxDynamicSharedMemorySize, SMEM_TOTAL);
    cudaFuncSetAttribute(mma_gemm<3>, cudaFuncAttributeMaxDynamicSharedMemorySize, SMEM_TOTAL);
    cudaFuncSetAttribute(mma_gemm<4>, cudaFuncAttributeMaxDynamicSharedMemorySize, SMEM_TOTAL);

    // launches 0..2: splits needed by the internal GEMM
    split_f32<0><<<(N_NODES * HS / 8 + 255) / 256, 256>>>(x, N_NODES * HS / 8);
    split_f32<1><<<(NW * HS / 8 + 255) / 256, 256>>>(W_w, NW * HS / 8);
    split_f32<2><<<(HS * HS / 8 + 255) / 256, 256>>>(U_r, HS * HS / 8);

    // launch index 3 (the one ncu profiles): the big internal-node GEMM
    {
        dim3 gi(NW / 128, (INTERNAL + 127) / 128);
        mma_gemm<0><<<gi, 256, SMEM_TOTAL>>>(INTERNAL, b_w, 0, 0, 0, nullptr);
    }

    split_f32<3><<<(HS * HS / 8 + 255) / 256, 256>>>(U_hc, HS * HS / 8);
    split_f32<4><<<(HS * HS / 8 + 255) / 256, 256>>>(U_z, HS * HS / 8);

    // leaves: fused GEMM -> h directly
    {
        dim3 gl(HS / 64, LEAVES / 128);
        mma_gemm<4><<<gl, 256, SMEM_TOTAL>>>(LEAVES, b_w, 0, INTERNAL, 0, h);
    }

    // level loop
    for (int l = 1; l <= 8; l++) {
        int d = 8 - l;
        int M = 1 << (2 * d);
        int base = S[d];
        int cbase = S[d + 1];

        child_sum<<<(M * 128 + 255) / 256, 256>>>(h, M * 128, cbase);

        dim3 g1(HS / 128, (M + 127) / 128);
        mma_gemm<1><<<g1, 256, SMEM_TOTAL>>>(M, nullptr, base, 0, 0, nullptr);
        mma_gemm<2><<<g1, 256, SMEM_TOTAL>>>(M, nullptr, base, 0, 0, nullptr);

        dim3 g3(HS / 128, (4 * M + 127) / 128);
        mma_gemm<3><<<g3, 256, SMEM_TOTAL>>>(4 * M, nullptr, base, cbase, 0, nullptr);

        combine<<<(M * 128 + 255) / 256, 256>>>(h, M * 128, base, cbase);
    }
}

// round 14
// speedup vs baseline: 2.6264x; 1.0030x over previous
#include <cuda_runtime.h>
#include <cuda_bf16.h>
#include <math.h>
#include <cstdint>

// ---------------- Problem constants (tree is fully regular) ----------------
#define HS 512
#define NW 1536
#define N_NODES 87381
#define INTERNAL 21845
#define LEAVES (N_NODES - INTERNAL)   // 65536
#define NPAD (N_NODES + 128)

typedef __nv_bfloat16 bf16;

// ---------------- Scratch (device globals; no allocation allowed) ----------
__device__ __align__(256) float g_wx[(size_t)INTERNAL * NW + 256]; // internal only
__device__ __align__(256) float g_hsum[16384 * HS];
__device__ __align__(256) float g_hcand[16384 * HS];

__device__ __align__(256) bf16 g_xhi[(size_t)NPAD * HS];
__device__ __align__(256) bf16 g_xlo[(size_t)NPAD * HS];
__device__ __align__(256) bf16 g_hhi[(size_t)NPAD * HS];
__device__ __align__(256) bf16 g_hlo[(size_t)NPAD * HS];
__device__ __align__(256) bf16 g_hshi[16384 * HS];
__device__ __align__(256) bf16 g_hslo[16384 * HS];
__device__ __align__(256) bf16 g_thi[16384 * HS];
__device__ __align__(256) bf16 g_tlo[16384 * HS];
__device__ __align__(256) bf16 g_wwhi[NW * HS];
__device__ __align__(256) bf16 g_wwlo[NW * HS];
__device__ __align__(256) bf16 g_urhi[HS * HS];
__device__ __align__(256) bf16 g_urlo[HS * HS];
__device__ __align__(256) bf16 g_uchi[HS * HS];
__device__ __align__(256) bf16 g_uclo[HS * HS];
__device__ __align__(256) bf16 g_uzhi[HS * HS];
__device__ __align__(256) bf16 g_uzlo[HS * HS];

__device__ __forceinline__ float sigf(float x) { return 1.0f / (1.0f + expf(-x)); }

__device__ __forceinline__ void mma16816(float* c, const uint32_t* a, const uint32_t* b) {
    asm volatile("mma.sync.aligned.m16n8k16.row.col.f32.bf16.bf16.f32 "
                 "{%0,%1,%2,%3}, {%4,%5,%6,%7}, {%8,%9}, {%0,%1,%2,%3};"
                 : "+f"(c[0]), "+f"(c[1]), "+f"(c[2]), "+f"(c[3])
                 : "r"(a[0]), "r"(a[1]), "r"(a[2]), "r"(a[3]), "r"(b[0]), "r"(b[1]));
}
__device__ __forceinline__ void ldm_x4(uint32_t* r, uint32_t addr) {
    asm volatile("ldmatrix.sync.aligned.m8n8.x4.shared.b16 {%0,%1,%2,%3}, [%4];"
                 : "=r"(r[0]), "=r"(r[1]), "=r"(r[2]), "=r"(r[3]) : "r"(addr));
}
__device__ __forceinline__ void cp16(uint32_t dst, const void* src) {
    asm volatile("cp.async.cg.shared.global [%0], [%1], 16;" :: "r"(dst), "l"(src));
}
#define CP_COMMIT() asm volatile("cp.async.commit_group;" ::: "memory")
#define CP_WAIT(n)  asm volatile("cp.async.wait_group %0;" :: "n"(n) : "memory")

// ---------------------------------------------------------------------------
// bf16-split GEMM: C[m][n] = sum_k A[m][k]*B[n][k], K=512, fp32 accum.
// C ≈ Ahi·Bhi + Ahi·Blo + Alo·Bhi.
// Block 128x128. BK=32, 2-stage cp.async (80KB -> 2 CTAs/SM).
// MODE 0: wx for internal nodes.  MODE 1: r-gate -> t.  MODE 2: h_cand.
// MODE 3: U_z GEMM with FUSED combine epilogue (z·h + sigmoid reduction over
//         each node's 4 edge-rows via shfl_xor, writes h + bf16 splits).
// MODE 4: leaf GEMM, fused leaf-h epilogue (wh & wz dual tiles).
// Tiles: 128 rows x 80B stride (64B data + 16B pad), ldmatrix conflict-free.
// ---------------------------------------------------------------------------
#define ROW_B   80
#define TILE_B  (128 * ROW_B)     // 10240
#define STAGE_B (4 * TILE_B)      // 40960
#define SMEM_TOTAL (2 * STAGE_B)  // 81920

template <int MODE>
__global__ __launch_bounds__(256, 2) void mma_gemm(int M, const float* __restrict__ bias,
                                                   int base, int arow0, int ncol0,
                                                   float* __restrict__ hout, int cbase) {
    const bf16* Ahi = (MODE == 0 || MODE == 4) ? g_xhi : (MODE == 1) ? g_hshi
                    : (MODE == 2) ? g_thi : g_hhi;
    const bf16* Alo = (MODE == 0 || MODE == 4) ? g_xlo : (MODE == 1) ? g_hslo
                    : (MODE == 2) ? g_tlo : g_hlo;
    const bf16* Bhi = (MODE == 0 || MODE == 4) ? g_wwhi : (MODE == 1) ? g_urhi
                    : (MODE == 2) ? g_uchi : g_uzhi;
    const bf16* Blo = (MODE == 0 || MODE == 4) ? g_wwlo : (MODE == 1) ? g_urlo
                    : (MODE == 2) ? g_uclo : g_uzlo;

    extern __shared__ __align__(16) char smem[];
    const uint32_t sb = (uint32_t)__cvta_generic_to_shared(smem);
    const int tid = threadIdx.x, lane = tid & 31, warp = tid >> 5;
    const int wm = warp & 3, wn = warp >> 2;          // 4x2 warp grid
    const int bm = blockIdx.y * 128;
    const int bn = blockIdx.x * 128;
    const int bcol0 = (MODE == 4) ? blockIdx.x * 64 : (ncol0 + bn);
    const int qr = lane >> 2;

    const int lrow   = (lane & 7) + ((lane >> 3) & 1) * 8;
    const int lcol16 = ((lane >> 4) & 1) * 16;

    float acc[2][8][4];
#pragma unroll
    for (int i = 0; i < 2; i++)
#pragma unroll
        for (int j = 0; j < 8; j++)
#pragma unroll
            for (int k = 0; k < 4; k++) acc[i][j][k] = 0.0f;

    const bf16* srcs[4] = {Ahi, Alo, Bhi, Blo};

    auto fill = [&](int s, int kb) {
#pragma unroll
        for (int t = 0; t < 4; t++) {
            const bf16* src = srcs[t];
#pragma unroll
            for (int j = 0; j < 2; j++) {
                int idx = tid + j * 256;              // 0..511
                int r = idx >> 2, c = idx & 3;
                int grow;
                if (t < 2) grow = arow0 + bm + r;
                else if (MODE == 4) grow = HS + ((r >> 6) & 1) * HS + bcol0 + (r & 63);
                else grow = bcol0 + r;
                cp16(sb + s * STAGE_B + t * TILE_B + r * ROW_B + c * 16,
                     src + (size_t)grow * 512 + kb * 32 + c * 8);
            }
        }
        CP_COMMIT();
    };

    fill(0, 0);

    for (int kb = 0; kb < 16; kb++) {
        if (kb + 1 < 16) { fill((kb + 1) & 1, kb + 1); CP_WAIT(1); }
        else             { CP_WAIT(0); }
        __syncthreads();

        const uint32_t st = sb + (kb & 1) * STAGE_B;
#pragma unroll
        for (int ks = 0; ks < 2; ks++) {
            uint32_t ah[2][4], al[2][4], bh[4][4], bl[4][4];
#pragma unroll
            for (int mi = 0; mi < 2; mi++) {
                uint32_t ra = st + (wm * 32 + mi * 16 + lrow) * ROW_B + ks * 32 + lcol16;
                ldm_x4(ah[mi], ra);
                ldm_x4(al[mi], ra + TILE_B);
            }
#pragma unroll
            for (int p = 0; p < 4; p++) {
                uint32_t rb = st + 2 * TILE_B + (wn * 64 + p * 16 + lrow) * ROW_B + ks * 32 + lcol16;
                ldm_x4(bh[p], rb);
                ldm_x4(bl[p], rb + TILE_B);
            }
#pragma unroll
            for (int ng = 0; ng < 8; ng++) {
                const int p = ng >> 1, s1 = ng & 1;
                uint32_t bfh[2] = {bh[p][s1], bh[p][s1 + 2]};
                uint32_t bfl[2] = {bl[p][s1], bl[p][s1 + 2]};
#pragma unroll
                for (int mi = 0; mi < 2; mi++) {
                    mma16816(acc[mi][ng], ah[mi], bfh);
                    mma16816(acc[mi][ng], ah[mi], bfl);
                    mma16816(acc[mi][ng], al[mi], bfh);
                }
            }
        }
        __syncthreads();
    }

    // ---------------- epilogues ----------------
    if (MODE == 4) {
        float* sf = (float*)smem;                      // 128 x 65 floats
#pragma unroll
        for (int mi = 0; mi < 2; mi++)
#pragma unroll
            for (int hh = 0; hh < 2; hh++)
#pragma unroll
                for (int ni = 0; ni < 8; ni++) {
                    if (wn == 1) {
                        int row = wm * 32 + mi * 16 + qr + hh * 8;
                        int colw = ni * 8 + (lane & 3) * 2;
                        sf[row * 65 + colw]     = acc[mi][ni][hh * 2 + 0];
                        sf[row * 65 + colw + 1] = acc[mi][ni][hh * 2 + 1];
                    }
                }
        __syncthreads();
        if (wn == 0) {
#pragma unroll
            for (int mi = 0; mi < 2; mi++)
#pragma unroll
                for (int hh = 0; hh < 2; hh++)
#pragma unroll
                    for (int ni = 0; ni < 8; ni++) {
                        int row = wm * 32 + mi * 16 + qr + hh * 8;
                        int colw = ni * 8 + (lane & 3) * 2;
                        int c = bcol0 + colw;
                        float wh0 = acc[mi][ni][hh * 2 + 0] + bias[HS + c];
                        float wh1 = acc[mi][ni][hh * 2 + 1] + bias[HS + c + 1];
                        float wz0 = sf[row * 65 + colw]     + bias[2 * HS + c];
                        float wz1 = sf[row * 65 + colw + 1] + bias[2 * HS + c + 1];
                        float v0 = (1.0f - sigf(wz0)) * tanhf(wh0);
                        float v1 = (1.0f - sigf(wz1)) * tanhf(wh1);
                        size_t node = (size_t)INTERNAL + bm + row;
                        *(float2*)(hout + node * HS + c) = make_float2(v0, v1);
                        bf16 b0 = __float2bfloat16_rn(v0), b1 = __float2bfloat16_rn(v1);
                        *(__nv_bfloat162*)(g_hhi + node * HS + c) = __halves2bfloat162(b0, b1);
                        *(__nv_bfloat162*)(g_hlo + node * HS + c) = __halves2bfloat162(
                            __float2bfloat16_rn(v0 - __bfloat162float(b0)),
                            __float2bfloat16_rn(v1 - __bfloat162float(b1)));
                    }
        }
        return;
    }

    if (MODE == 3) {
        // Fused combine: rows are edges (4 consecutive = one node, same warp).
        const int Medges = M;
#pragma unroll
        for (int mi = 0; mi < 2; mi++) {
#pragma unroll
            for (int hh = 0; hh < 2; hh++) {
#pragma unroll
                for (int ni = 0; ni < 8; ni++) {
                    int row  = wm * 32 + mi * 16 + qr + hh * 8;
                    int erow = bm + row;                      // within-level edge
                    int col  = bn + wn * 64 + ni * 8 + (lane & 3) * 2;
                    bool ok = (erow < Medges);
                    int node = erow >> 2;
                    float z0 = acc[mi][ni][hh * 2 + 0];
                    float z1 = acc[mi][ni][hh * 2 + 1];
                    float2 hv = make_float2(0.f, 0.f), wz = make_float2(0.f, 0.f);
                    if (ok) {
                        hv = *(const float2*)(hout + (size_t)(cbase + erow) * HS + col);
                        wz = *(const float2*)(g_wx + (size_t)(base + node) * NW + 2 * HS + col);
                    }
                    float p0 = ok ? z0 * hv.x : 0.f;
                    float p1 = ok ? z1 * hv.y : 0.f;
                    float s0 = ok ? sigf(z0 + wz.x) : 0.f;
                    float s1 = ok ? sigf(z1 + wz.y) : 0.f;
                    p0 += __shfl_xor_sync(~0u, p0, 4);  p0 += __shfl_xor_sync(~0u, p0, 8);
                    p1 += __shfl_xor_sync(~0u, p1, 4);  p1 += __shfl_xor_sync(~0u, p1, 8);
                    s0 += __shfl_xor_sync(~0u, s0, 4);  s0 += __shfl_xor_sync(~0u, s0, 8);
                    s1 += __shfl_xor_sync(~0u, s1, 4);  s1 += __shfl_xor_sync(~0u, s1, 8);
                    if (ok && (qr & 3) == 0) {
                        float2 hc = *(const float2*)(g_hcand + (size_t)node * HS + col);
                        float v0 = p0 + (1.0f - s0) * hc.x;
                        float v1 = p1 + (1.0f - s1) * hc.y;
                        *(float2*)(hout + (size_t)(base + node) * HS + col) = make_float2(v0, v1);
                        bf16 b0 = __float2bfloat16_rn(v0), b1 = __float2bfloat16_rn(v1);
                        *(__nv_bfloat162*)(g_hhi + (size_t)(base + node) * HS + col) =
                            __halves2bfloat162(b0, b1);
                        *(__nv_bfloat162*)(g_hlo + (size_t)(base + node) * HS + col) =
                            __halves2bfloat162(
                                __float2bfloat16_rn(v0 - __bfloat162float(b0)),
                                __float2bfloat16_rn(v1 - __bfloat162float(b1)));
                    }
                }
            }
        }
        return;
    }

#pragma unroll
    for (int mi = 0; mi < 2; mi++) {
#pragma unroll
        for (int hh = 0; hh < 2; hh++) {
            int m = bm + wm * 32 + mi * 16 + qr + hh * 8;
            if (m >= M) continue;
#pragma unroll
            for (int ni = 0; ni < 8; ni++) {
                int col = bn + wn * 64 + ni * 8 + (lane & 3) * 2;
                float v0 = acc[mi][ni][hh * 2 + 0];
                float v1 = acc[mi][ni][hh * 2 + 1];
                if (MODE == 0) {
                    float2 bb = *(const float2*)(bias + ncol0 + col);
                    *(float2*)(g_wx + (size_t)(arow0 + m) * NW + ncol0 + col) =
                        make_float2(v0 + bb.x, v1 + bb.y);
                } else if (MODE == 1) {
                    const float2 wr = *(const float2*)(g_wx + (size_t)(base + m) * NW + col);
                    const float2 hs = *(const float2*)(g_hsum + (size_t)m * HS + col);
                    float t0 = sigf(wr.x + v0) * hs.x;
                    float t1 = sigf(wr.y + v1) * hs.y;
                    bf16 h0 = __float2bfloat16_rn(t0), h1 = __float2bfloat16_rn(t1);
                    *(__nv_bfloat162*)(g_thi + (size_t)m * HS + col) = __halves2bfloat162(h0, h1);
                    *(__nv_bfloat162*)(g_tlo + (size_t)m * HS + col) = __halves2bfloat162(
                        __float2bfloat16_rn(t0 - __bfloat162float(h0)),
                        __float2bfloat16_rn(t1 - __bfloat162float(h1)));
                } else if (MODE == 2) {
                    const float2 wh = *(const float2*)(g_wx + (size_t)(base + m) * NW + HS + col);
                    *(float2*)(g_hcand + (size_t)m * HS + col) =
                        make_float2(tanhf(wh.x + v0), tanhf(wh.y + v1));
                }
            }
        }
    }
}

// ---------------- elementwise kernels (vectorized) --------------------------
template <int WHICH>
__global__ void split_f32(const float* __restrict__ in, int n8) {
    int i = blockIdx.x * blockDim.x + threadIdx.x;
    if (i >= n8) return;
    bf16* hi = (WHICH == 0) ? g_xhi : (WHICH == 1) ? g_wwhi
             : (WHICH == 2) ? g_urhi : (WHICH == 3) ? g_uchi : g_uzhi;
    bf16* lo = (WHICH == 0) ? g_xlo : (WHICH == 1) ? g_wwlo
             : (WHICH == 2) ? g_urlo : (WHICH == 3) ? g_uclo : g_uzlo;
    float4 a = ((const float4*)in)[2 * i];
    float4 b = ((const float4*)in)[2 * i + 1];
    float v[8] = {a.x, a.y, a.z, a.w, b.x, b.y, b.z, b.w};
    __nv_bfloat162 hw[4], lw[4];
#pragma unroll
    for (int j = 0; j < 4; j++) {
        bf16 h0 = __float2bfloat16_rn(v[2 * j]);
        bf16 h1 = __float2bfloat16_rn(v[2 * j + 1]);
        hw[j] = __halves2bfloat162(h0, h1);
        lw[j] = __halves2bfloat162(
            __float2bfloat16_rn(v[2 * j] - __bfloat162float(h0)),
            __float2bfloat16_rn(v[2 * j + 1] - __bfloat162float(h1)));
    }
    ((uint4*)hi)[i] = *(uint4*)hw;
    ((uint4*)lo)[i] = *(uint4*)lw;
}

__global__ void child_sum(const float* __restrict__ h, int n4, int cbase) {
    int idx = blockIdx.x * blockDim.x + threadIdx.x;
    if (idx >= n4) return;
    int r = idx >> 7, c4 = idx & 127;
    const float4* hc = (const float4*)(h + (size_t)(cbase + 4 * r) * HS) + c4;
    float4 s0 = hc[0], s1 = hc[128], s2 = hc[256], s3 = hc[384];
    float4 v = make_float4(s0.x + s1.x + s2.x + s3.x, s0.y + s1.y + s2.y + s3.y,
                           s0.z + s1.z + s2.z + s3.z, s0.w + s1.w + s2.w + s3.w);
    ((float4*)g_hsum)[idx] = v;
    float vv[4] = {v.x, v.y, v.z, v.w};
    __nv_bfloat162 hw[2], lw[2];
#pragma unroll
    for (int j = 0; j < 2; j++) {
        bf16 h0 = __float2bfloat16_rn(vv[2 * j]);
        bf16 h1 = __float2bfloat16_rn(vv[2 * j + 1]);
        hw[j] = __halves2bfloat162(h0, h1);
        lw[j] = __halves2bfloat162(
            __float2bfloat16_rn(vv[2 * j] - __bfloat162float(h0)),
            __float2bfloat16_rn(vv[2 * j + 1] - __bfloat162float(h1)));
    }
    ((uint2*)g_hshi)[idx] = *(uint2*)hw;
    ((uint2*)g_hslo)[idx] = *(uint2*)lw;
}

// ---------------------------------------------------------------------------
extern "C" void kernel_launch(void* const* d_in, const int* in_sizes, int n_in,
                              void* d_out, int out_size) {
    const float* x    = (const float*)d_in[0];
    const float* W_w  = (const float*)d_in[1];
    const float* b_w  = (const float*)d_in[2];
    const float* U_r  = (const float*)d_in[3];
    const float* U_hc = (const float*)d_in[4];
    const float* U_z  = (const float*)d_in[5];
    float* h = (float*)d_out;

    static const int S[10] = {0, 1, 5, 21, 85, 341, 1365, 5461, 21845, 87381};

    cudaFuncSetAttribute(mma_gemm<0>, cudaFuncAttributeMaxDynamicSharedMemorySize, SMEM_TOTAL);
    cudaFuncSetAttribute(mma_gemm<1>, cudaFuncAttributeMaxDynamicSharedMemorySize, SMEM_TOTAL);
    cudaFuncSetAttribute(mma_gemm<2>, cudaFuncAttributeMaxDynamicSharedMemorySize, SMEM_TOTAL);
    cudaFuncSetAttribute(mma_gemm<3>, cudaFuncAttributeMaxDynamicSharedMemorySize, SMEM_TOTAL);
    cudaFuncSetAttribute(mma_gemm<4>, cudaFuncAttributeMaxDynamicSharedMemorySize, SMEM_TOTAL);

    // launches 0..2: splits needed by the internal GEMM
    split_f32<0><<<(N_NODES * HS / 8 + 255) / 256, 256>>>(x, N_NODES * HS / 8);
    split_f32<1><<<(NW * HS / 8 + 255) / 256, 256>>>(W_w, NW * HS / 8);
    split_f32<2><<<(HS * HS / 8 + 255) / 256, 256>>>(U_r, HS * HS / 8);

    // launch index 3 (ncu profiles this): the big internal-node GEMM
    {
        dim3 gi(NW / 128, (INTERNAL + 127) / 128);
        mma_gemm<0><<<gi, 256, SMEM_TOTAL>>>(INTERNAL, b_w, 0, 0, 0, nullptr, 0);
    }

    split_f32<3><<<(HS * HS / 8 + 255) / 256, 256>>>(U_hc, HS * HS / 8);
    split_f32<4><<<(HS * HS / 8 + 255) / 256, 256>>>(U_z, HS * HS / 8);

    // leaves: fused GEMM -> h directly
    {
        dim3 gl(HS / 64, LEAVES / 128);
        mma_gemm<4><<<gl, 256, SMEM_TOTAL>>>(LEAVES, b_w, 0, INTERNAL, 0, h, 0);
    }

    // level loop
    for (int l = 1; l <= 8; l++) {
        int d = 8 - l;
        int M = 1 << (2 * d);
        int base = S[d];
        int cbase = S[d + 1];

        child_sum<<<(M * 128 + 255) / 256, 256>>>(h, M * 128, cbase);

        dim3 g1(HS / 128, (M + 127) / 128);
        mma_gemm<1><<<g1, 256, SMEM_TOTAL>>>(M, nullptr, base, 0, 0, nullptr, 0);
        mma_gemm<2><<<g1, 256, SMEM_TOTAL>>>(M, nullptr, base, 0, 0, nullptr, 0);

        // U_z GEMM over 4M edges with fused combine epilogue
        dim3 g3(HS / 128, (4 * M + 127) / 128);
        mma_gemm<3><<<g3, 256, SMEM_TOTAL>>>(4 * M, nullptr, base, cbase, 0, h, cbase);
    }
}

// round 15
// speedup vs baseline: 2.8793x; 1.0963x over previous
#include <cuda_runtime.h>
#include <cuda_bf16.h>
#include <math.h>
#include <cstdint>

// ---------------- Problem constants (tree is fully regular) ----------------
#define HS 512
#define NW 1536
#define N_NODES 87381
#define INTERNAL 21845
#define LEAVES (N_NODES - INTERNAL)   // 65536
#define NPAD (N_NODES + 128)

typedef __nv_bfloat16 bf16;

// ---------------- Scratch (device globals; no allocation allowed) ----------
__device__ __align__(256) float g_wx[(size_t)INTERNAL * NW + 256]; // internal only
__device__ __align__(256) float g_hsum[16384 * HS];
__device__ __align__(256) float g_hcand[16384 * HS];

__device__ __align__(256) bf16 g_xhi[(size_t)NPAD * HS];
__device__ __align__(256) bf16 g_xlo[(size_t)NPAD * HS];
__device__ __align__(256) bf16 g_hhi[(size_t)NPAD * HS];
__device__ __align__(256) bf16 g_hlo[(size_t)NPAD * HS];
__device__ __align__(256) bf16 g_hshi[16384 * HS];
__device__ __align__(256) bf16 g_hslo[16384 * HS];
__device__ __align__(256) bf16 g_thi[16384 * HS];
__device__ __align__(256) bf16 g_tlo[16384 * HS];
__device__ __align__(256) bf16 g_wwhi[NW * HS];
__device__ __align__(256) bf16 g_wwlo[NW * HS];
__device__ __align__(256) bf16 g_urhi[HS * HS];
__device__ __align__(256) bf16 g_urlo[HS * HS];
__device__ __align__(256) bf16 g_uchi[HS * HS];
__device__ __align__(256) bf16 g_uclo[HS * HS];
__device__ __align__(256) bf16 g_uzhi[HS * HS];
__device__ __align__(256) bf16 g_uzlo[HS * HS];

__device__ __forceinline__ float sigf(float x) { return 1.0f / (1.0f + expf(-x)); }

__device__ __forceinline__ void mma16816(float* c, const uint32_t* a, const uint32_t* b) {
    asm volatile("mma.sync.aligned.m16n8k16.row.col.f32.bf16.bf16.f32 "
                 "{%0,%1,%2,%3}, {%4,%5,%6,%7}, {%8,%9}, {%0,%1,%2,%3};"
                 : "+f"(c[0]), "+f"(c[1]), "+f"(c[2]), "+f"(c[3])
                 : "r"(a[0]), "r"(a[1]), "r"(a[2]), "r"(a[3]), "r"(b[0]), "r"(b[1]));
}
__device__ __forceinline__ void ldm_x4(uint32_t* r, uint32_t addr) {
    asm volatile("ldmatrix.sync.aligned.m8n8.x4.shared.b16 {%0,%1,%2,%3}, [%4];"
                 : "=r"(r[0]), "=r"(r[1]), "=r"(r[2]), "=r"(r[3]) : "r"(addr));
}
__device__ __forceinline__ void cp16(uint32_t dst, const void* src) {
    asm volatile("cp.async.cg.shared.global [%0], [%1], 16;" :: "r"(dst), "l"(src));
}
#define CP_COMMIT() asm volatile("cp.async.commit_group;" ::: "memory")
#define CP_WAIT(n)  asm volatile("cp.async.wait_group %0;" :: "n"(n) : "memory")

// ---------------------------------------------------------------------------
// bf16-split GEMM: C[m][n] = sum_k A[m][k]*B[n][k], K=512, fp32 accum.
// C ≈ Ahi·Bhi + Ahi·Blo + Alo·Bhi.
// Block 128x128. BK=32, 3-stage cp.async pipeline (96KB -> 2 CTAs/SM).
// smem tile: 128 rows x 64B, chunk swizzle c ^ ((r>>1)&3) (16B chunks):
//   ldmatrix phase rows y=0..7 hit words 4*(ch^{0..3}) split even/odd rows
//   across the two 16-word halves -> conflict-free.
// MODE 0: wx for internal nodes.  MODE 1: r-gate -> t.  MODE 2: h_cand.
// MODE 3: U_z GEMM + FUSED combine epilogue (shfl_xor over 4 edge rows).
// MODE 4: leaf GEMM, fused leaf-h epilogue (wh & wz dual tiles).
// ---------------------------------------------------------------------------
#define ROW_B   64
#define TILE_B  (128 * ROW_B)     // 8192
#define STAGE_B (4 * TILE_B)      // 32768
#define SMEM_TOTAL (3 * STAGE_B)  // 98304

template <int MODE>
__global__ __launch_bounds__(256, 2) void mma_gemm(int M, const float* __restrict__ bias,
                                                   int base, int arow0, int ncol0,
                                                   float* __restrict__ hout, int cbase) {
    const bf16* Ahi = (MODE == 0 || MODE == 4) ? g_xhi : (MODE == 1) ? g_hshi
                    : (MODE == 2) ? g_thi : g_hhi;
    const bf16* Alo = (MODE == 0 || MODE == 4) ? g_xlo : (MODE == 1) ? g_hslo
                    : (MODE == 2) ? g_tlo : g_hlo;
    const bf16* Bhi = (MODE == 0 || MODE == 4) ? g_wwhi : (MODE == 1) ? g_urhi
                    : (MODE == 2) ? g_uchi : g_uzhi;
    const bf16* Blo = (MODE == 0 || MODE == 4) ? g_wwlo : (MODE == 1) ? g_urlo
                    : (MODE == 2) ? g_uclo : g_uzlo;

    extern __shared__ __align__(16) char smem[];
    const uint32_t sb = (uint32_t)__cvta_generic_to_shared(smem);
    const int tid = threadIdx.x, lane = tid & 31, warp = tid >> 5;
    const int wm = warp & 3, wn = warp >> 2;          // 4x2 warp grid
    const int bm = blockIdx.y * 128;
    const int bn = blockIdx.x * 128;
    const int bcol0 = (MODE == 4) ? blockIdx.x * 64 : (ncol0 + bn);
    const int qr = lane >> 2;

    const int lrow = lane & 15;                       // fragment source row
    const int lchv = (lane >> 4) & 1;                 // chunk +0/+1
    const int lsel = (lrow >> 1) & 3;                 // swizzle selector

    float acc[2][8][4];
#pragma unroll
    for (int i = 0; i < 2; i++)
#pragma unroll
        for (int j = 0; j < 8; j++)
#pragma unroll
            for (int k = 0; k < 4; k++) acc[i][j][k] = 0.0f;

    const bf16* srcs[4] = {Ahi, Alo, Bhi, Blo};

    auto fill = [&](int s, int kb) {
#pragma unroll
        for (int t = 0; t < 4; t++) {
            const bf16* src = srcs[t];
#pragma unroll
            for (int j = 0; j < 2; j++) {
                int idx = tid + j * 256;              // 0..511
                int r = idx >> 2, c = idx & 3;
                int grow;
                if (t < 2) grow = arow0 + bm + r;
                else if (MODE == 4) grow = HS + ((r >> 6) & 1) * HS + bcol0 + (r & 63);
                else grow = bcol0 + r;
                cp16(sb + s * STAGE_B + t * TILE_B + r * ROW_B +
                         ((c ^ ((r >> 1) & 3)) << 4),
                     src + (size_t)grow * 512 + kb * 32 + c * 8);
            }
        }
        CP_COMMIT();
    };

    fill(0, 0);
    fill(1, 1);

    for (int kb = 0; kb < 16; kb++) {
        if (kb < 14)      { fill((kb + 2) % 3, kb + 2); CP_WAIT(2); }
        else if (kb == 14){ CP_WAIT(1); }
        else              { CP_WAIT(0); }
        __syncthreads();

        const uint32_t st = sb + (kb % 3) * STAGE_B;
#pragma unroll
        for (int ks = 0; ks < 2; ks++) {
            const int ch = 2 * ks + lchv;
            uint32_t ah[2][4], al[2][4], bh[4][4], bl[4][4];
#pragma unroll
            for (int mi = 0; mi < 2; mi++) {
                uint32_t ra = st + (wm * 32 + mi * 16 + lrow) * ROW_B + ((ch ^ lsel) << 4);
                ldm_x4(ah[mi], ra);
                ldm_x4(al[mi], ra + TILE_B);
            }
#pragma unroll
            for (int p = 0; p < 4; p++) {
                uint32_t rb = st + 2 * TILE_B + (wn * 64 + p * 16 + lrow) * ROW_B + ((ch ^ lsel) << 4);
                ldm_x4(bh[p], rb);
                ldm_x4(bl[p], rb + TILE_B);
            }
#pragma unroll
            for (int ng = 0; ng < 8; ng++) {
                const int p = ng >> 1, s1 = ng & 1;
                uint32_t bfh[2] = {bh[p][s1], bh[p][s1 + 2]};
                uint32_t bfl[2] = {bl[p][s1], bl[p][s1 + 2]};
#pragma unroll
                for (int mi = 0; mi < 2; mi++) {
                    mma16816(acc[mi][ng], ah[mi], bfh);
                    mma16816(acc[mi][ng], ah[mi], bfl);
                    mma16816(acc[mi][ng], al[mi], bfh);
                }
            }
        }
        __syncthreads();
    }

    // ---------------- epilogues ----------------
    if (MODE == 4) {
        float* sf = (float*)smem;                      // 128 x 65 floats
#pragma unroll
        for (int mi = 0; mi < 2; mi++)
#pragma unroll
            for (int hh = 0; hh < 2; hh++)
#pragma unroll
                for (int ni = 0; ni < 8; ni++) {
                    if (wn == 1) {
                        int row = wm * 32 + mi * 16 + qr + hh * 8;
                        int colw = ni * 8 + (lane & 3) * 2;
                        sf[row * 65 + colw]     = acc[mi][ni][hh * 2 + 0];
                        sf[row * 65 + colw + 1] = acc[mi][ni][hh * 2 + 1];
                    }
                }
        __syncthreads();
        if (wn == 0) {
#pragma unroll
            for (int mi = 0; mi < 2; mi++)
#pragma unroll
                for (int hh = 0; hh < 2; hh++)
#pragma unroll
                    for (int ni = 0; ni < 8; ni++) {
                        int row = wm * 32 + mi * 16 + qr + hh * 8;
                        int colw = ni * 8 + (lane & 3) * 2;
                        int c = bcol0 + colw;
                        float wh0 = acc[mi][ni][hh * 2 + 0] + bias[HS + c];
                        float wh1 = acc[mi][ni][hh * 2 + 1] + bias[HS + c + 1];
                        float wz0 = sf[row * 65 + colw]     + bias[2 * HS + c];
                        float wz1 = sf[row * 65 + colw + 1] + bias[2 * HS + c + 1];
                        float v0 = (1.0f - sigf(wz0)) * tanhf(wh0);
                        float v1 = (1.0f - sigf(wz1)) * tanhf(wh1);
                        size_t node = (size_t)INTERNAL + bm + row;
                        *(float2*)(hout + node * HS + c) = make_float2(v0, v1);
                        bf16 b0 = __float2bfloat16_rn(v0), b1 = __float2bfloat16_rn(v1);
                        *(__nv_bfloat162*)(g_hhi + node * HS + c) = __halves2bfloat162(b0, b1);
                        *(__nv_bfloat162*)(g_hlo + node * HS + c) = __halves2bfloat162(
                            __float2bfloat16_rn(v0 - __bfloat162float(b0)),
                            __float2bfloat16_rn(v1 - __bfloat162float(b1)));
                    }
        }
        return;
    }

    if (MODE == 3) {
        const int Medges = M;
#pragma unroll
        for (int mi = 0; mi < 2; mi++) {
#pragma unroll
            for (int hh = 0; hh < 2; hh++) {
#pragma unroll
                for (int ni = 0; ni < 8; ni++) {
                    int row  = wm * 32 + mi * 16 + qr + hh * 8;
                    int erow = bm + row;                      // within-level edge
                    int col  = bn + wn * 64 + ni * 8 + (lane & 3) * 2;
                    bool ok = (erow < Medges);
                    int node = erow >> 2;
                    float z0 = acc[mi][ni][hh * 2 + 0];
                    float z1 = acc[mi][ni][hh * 2 + 1];
                    float2 hv = make_float2(0.f, 0.f), wz = make_float2(0.f, 0.f);
                    if (ok) {
                        hv = *(const float2*)(hout + (size_t)(cbase + erow) * HS + col);
                        wz = *(const float2*)(g_wx + (size_t)(base + node) * NW + 2 * HS + col);
                    }
                    float p0 = ok ? z0 * hv.x : 0.f;
                    float p1 = ok ? z1 * hv.y : 0.f;
                    float s0 = ok ? sigf(z0 + wz.x) : 0.f;
                    float s1 = ok ? sigf(z1 + wz.y) : 0.f;
                    p0 += __shfl_xor_sync(~0u, p0, 4);  p0 += __shfl_xor_sync(~0u, p0, 8);
                    p1 += __shfl_xor_sync(~0u, p1, 4);  p1 += __shfl_xor_sync(~0u, p1, 8);
                    s0 += __shfl_xor_sync(~0u, s0, 4);  s0 += __shfl_xor_sync(~0u, s0, 8);
                    s1 += __shfl_xor_sync(~0u, s1, 4);  s1 += __shfl_xor_sync(~0u, s1, 8);
                    if (ok && (qr & 3) == 0) {
                        float2 hc = *(const float2*)(g_hcand + (size_t)node * HS + col);
                        float v0 = p0 + (1.0f - s0) * hc.x;
                        float v1 = p1 + (1.0f - s1) * hc.y;
                        *(float2*)(hout + (size_t)(base + node) * HS + col) = make_float2(v0, v1);
                        bf16 b0 = __float2bfloat16_rn(v0), b1 = __float2bfloat16_rn(v1);
                        *(__nv_bfloat162*)(g_hhi + (size_t)(base + node) * HS + col) =
                            __halves2bfloat162(b0, b1);
                        *(__nv_bfloat162*)(g_hlo + (size_t)(base + node) * HS + col) =
                            __halves2bfloat162(
                                __float2bfloat16_rn(v0 - __bfloat162float(b0)),
                                __float2bfloat16_rn(v1 - __bfloat162float(b1)));
                    }
                }
            }
        }
        return;
    }

#pragma unroll
    for (int mi = 0; mi < 2; mi++) {
#pragma unroll
        for (int hh = 0; hh < 2; hh++) {
            int m = bm + wm * 32 + mi * 16 + qr + hh * 8;
            if (m >= M) continue;
#pragma unroll
            for (int ni = 0; ni < 8; ni++) {
                int col = bn + wn * 64 + ni * 8 + (lane & 3) * 2;
                float v0 = acc[mi][ni][hh * 2 + 0];
                float v1 = acc[mi][ni][hh * 2 + 1];
                if (MODE == 0) {
                    float2 bb = *(const float2*)(bias + ncol0 + col);
                    *(float2*)(g_wx + (size_t)(arow0 + m) * NW + ncol0 + col) =
                        make_float2(v0 + bb.x, v1 + bb.y);
                } else if (MODE == 1) {
                    const float2 wr = *(const float2*)(g_wx + (size_t)(base + m) * NW + col);
                    const float2 hs = *(const float2*)(g_hsum + (size_t)m * HS + col);
                    float t0 = sigf(wr.x + v0) * hs.x;
                    float t1 = sigf(wr.y + v1) * hs.y;
                    bf16 h0 = __float2bfloat16_rn(t0), h1 = __float2bfloat16_rn(t1);
                    *(__nv_bfloat162*)(g_thi + (size_t)m * HS + col) = __halves2bfloat162(h0, h1);
                    *(__nv_bfloat162*)(g_tlo + (size_t)m * HS + col) = __halves2bfloat162(
                        __float2bfloat16_rn(t0 - __bfloat162float(h0)),
                        __float2bfloat16_rn(t1 - __bfloat162float(h1)));
                } else if (MODE == 2) {
                    const float2 wh = *(const float2*)(g_wx + (size_t)(base + m) * NW + HS + col);
                    *(float2*)(g_hcand + (size_t)m * HS + col) =
                        make_float2(tanhf(wh.x + v0), tanhf(wh.y + v1));
                }
            }
        }
    }
}

// ---------------- elementwise kernels (vectorized) --------------------------
template <int WHICH>
__global__ void split_f32(const float* __restrict__ in, int n8) {
    int i = blockIdx.x * blockDim.x + threadIdx.x;
    if (i >= n8) return;
    bf16* hi = (WHICH == 0) ? g_xhi : (WHICH == 1) ? g_wwhi
             : (WHICH == 2) ? g_urhi : (WHICH == 3) ? g_uchi : g_uzhi;
    bf16* lo = (WHICH == 0) ? g_xlo : (WHICH == 1) ? g_wwlo
             : (WHICH == 2) ? g_urlo : (WHICH == 3) ? g_uclo : g_uzlo;
    float4 a = ((const float4*)in)[2 * i];
    float4 b = ((const float4*)in)[2 * i + 1];
    float v[8] = {a.x, a.y, a.z, a.w, b.x, b.y, b.z, b.w};
    __nv_bfloat162 hw[4], lw[4];
#pragma unroll
    for (int j = 0; j < 4; j++) {
        bf16 h0 = __float2bfloat16_rn(v[2 * j]);
        bf16 h1 = __float2bfloat16_rn(v[2 * j + 1]);
        hw[j] = __halves2bfloat162(h0, h1);
        lw[j] = __halves2bfloat162(
            __float2bfloat16_rn(v[2 * j] - __bfloat162float(h0)),
            __float2bfloat16_rn(v[2 * j + 1] - __bfloat162float(h1)));
    }
    ((uint4*)hi)[i] = *(uint4*)hw;
    ((uint4*)lo)[i] = *(uint4*)lw;
}

__global__ void child_sum(const float* __restrict__ h, int n4, int cbase) {
    int idx = blockIdx.x * blockDim.x + threadIdx.x;
    if (idx >= n4) return;
    int r = idx >> 7, c4 = idx & 127;
    const float4* hc = (const float4*)(h + (size_t)(cbase + 4 * r) * HS) + c4;
    float4 s0 = hc[0], s1 = hc[128], s2 = hc[256], s3 = hc[384];
    float4 v = make_float4(s0.x + s1.x + s2.x + s3.x, s0.y + s1.y + s2.y + s3.y,
                           s0.z + s1.z + s2.z + s3.z, s0.w + s1.w + s2.w + s3.w);
    ((float4*)g_hsum)[idx] = v;
    float vv[4] = {v.x, v.y, v.z, v.w};
    __nv_bfloat162 hw[2], lw[2];
#pragma unroll
    for (int j = 0; j < 2; j++) {
        bf16 h0 = __float2bfloat16_rn(vv[2 * j]);
        bf16 h1 = __float2bfloat16_rn(vv[2 * j + 1]);
        hw[j] = __halves2bfloat162(h0, h1);
        lw[j] = __halves2bfloat162(
            __float2bfloat16_rn(vv[2 * j] - __bfloat162float(h0)),
            __float2bfloat16_rn(vv[2 * j + 1] - __bfloat162float(h1)));
    }
    ((uint2*)g_hshi)[idx] = *(uint2*)hw;
    ((uint2*)g_hslo)[idx] = *(uint2*)lw;
}

// ---------------------------------------------------------------------------
extern "C" void kernel_launch(void* const* d_in, const int* in_sizes, int n_in,
                              void* d_out, int out_size) {
    const float* x    = (const float*)d_in[0];
    const float* W_w  = (const float*)d_in[1];
    const float* b_w  = (const float*)d_in[2];
    const float* U_r  = (const float*)d_in[3];
    const float* U_hc = (const float*)d_in[4];
    const float* U_z  = (const float*)d_in[5];
    float* h = (float*)d_out;

    static const int S[10] = {0, 1, 5, 21, 85, 341, 1365, 5461, 21845, 87381};

    cudaFuncSetAttribute(mma_gemm<0>, cudaFuncAttributeMaxDynamicSharedMemorySize, SMEM_TOTAL);
    cudaFuncSetAttribute(mma_gemm<1>, cudaFuncAttributeMaxDynamicSharedMemorySize, SMEM_TOTAL);
    cudaFuncSetAttribute(mma_gemm<2>, cudaFuncAttributeMaxDynamicSharedMemorySize, SMEM_TOTAL);
    cudaFuncSetAttribute(mma_gemm<3>, cudaFuncAttributeMaxDynamicSharedMemorySize, SMEM_TOTAL);
    cudaFuncSetAttribute(mma_gemm<4>, cudaFuncAttributeMaxDynamicSharedMemorySize, SMEM_TOTAL);

    // launches 0..2: splits needed by the leaf GEMM
    split_f32<0><<<(N_NODES * HS / 8 + 255) / 256, 256>>>(x, N_NODES * HS / 8);
    split_f32<1><<<(NW * HS / 8 + 255) / 256, 256>>>(W_w, NW * HS / 8);
    split_f32<2><<<(HS * HS / 8 + 255) / 256, 256>>>(U_r, HS * HS / 8);

    // launch index 3 (ncu profiles this): the LEAF GEMM (largest kernel)
    {
        dim3 gl(HS / 64, LEAVES / 128);
        mma_gemm<4><<<gl, 256, SMEM_TOTAL>>>(LEAVES, b_w, 0, INTERNAL, 0, h, 0);
    }

    // internal-node GEMM
    {
        dim3 gi(NW / 128, (INTERNAL + 127) / 128);
        mma_gemm<0><<<gi, 256, SMEM_TOTAL>>>(INTERNAL, b_w, 0, 0, 0, nullptr, 0);
    }

    split_f32<3><<<(HS * HS / 8 + 255) / 256, 256>>>(U_hc, HS * HS / 8);
    split_f32<4><<<(HS * HS / 8 + 255) / 256, 256>>>(U_z, HS * HS / 8);

    // level loop
    for (int l = 1; l <= 8; l++) {
        int d = 8 - l;
        int M = 1 << (2 * d);
        int base = S[d];
        int cbase = S[d + 1];

        child_sum<<<(M * 128 + 255) / 256, 256>>>(h, M * 128, cbase);

        dim3 g1(HS / 128, (M + 127) / 128);
        mma_gemm<1><<<g1, 256, SMEM_TOTAL>>>(M, nullptr, base, 0, 0, nullptr, 0);
        mma_gemm<2><<<g1, 256, SMEM_TOTAL>>>(M, nullptr, base, 0, 0, nullptr, 0);

        // U_z GEMM over 4M edges with fused combine epilogue
        dim3 g3(HS / 128, (4 * M + 127) / 128);
        mma_gemm<3><<<g3, 256, SMEM_TOTAL>>>(4 * M, nullptr, base, cbase, 0, h, cbase);
    }
}

// round 16
// speedup vs baseline: 3.0093x; 1.0451x over previous
#include <cuda_runtime.h>
#include <cuda_bf16.h>
#include <math.h>
#include <cstdint>

// ---------------- Problem constants (tree is fully regular) ----------------
#define HS 512
#define NW 1536
#define N_NODES 87381
#define INTERNAL 21845
#define LEAVES (N_NODES - INTERNAL)   // 65536
#define NPAD (N_NODES + 128)

typedef __nv_bfloat16 bf16;

// ---------------- Scratch (device globals; no allocation allowed) ----------
__device__ __align__(256) float g_wx[(size_t)INTERNAL * NW + 256]; // internal only
__device__ __align__(256) float g_hsum[16384 * HS];
__device__ __align__(256) float g_hcand[16384 * HS];

__device__ __align__(256) bf16 g_xhi[(size_t)NPAD * HS];
__device__ __align__(256) bf16 g_xlo[(size_t)NPAD * HS];
__device__ __align__(256) bf16 g_hhi[(size_t)NPAD * HS];
__device__ __align__(256) bf16 g_hlo[(size_t)NPAD * HS];
__device__ __align__(256) bf16 g_hshi[16384 * HS];
__device__ __align__(256) bf16 g_hslo[16384 * HS];
__device__ __align__(256) bf16 g_thi[16384 * HS];
__device__ __align__(256) bf16 g_tlo[16384 * HS];
__device__ __align__(256) bf16 g_wwhi[NW * HS];
__device__ __align__(256) bf16 g_wwlo[NW * HS];
__device__ __align__(256) bf16 g_urhi[HS * HS];
__device__ __align__(256) bf16 g_urlo[HS * HS];
__device__ __align__(256) bf16 g_uchi[HS * HS];
__device__ __align__(256) bf16 g_uclo[HS * HS];
__device__ __align__(256) bf16 g_uzhi[HS * HS];
__device__ __align__(256) bf16 g_uzlo[HS * HS];

__device__ __forceinline__ float sigf(float x) { return 1.0f / (1.0f + expf(-x)); }

__device__ __forceinline__ void mma16816(float* c, const uint32_t* a, const uint32_t* b) {
    asm volatile("mma.sync.aligned.m16n8k16.row.col.f32.bf16.bf16.f32 "
                 "{%0,%1,%2,%3}, {%4,%5,%6,%7}, {%8,%9}, {%0,%1,%2,%3};"
                 : "+f"(c[0]), "+f"(c[1]), "+f"(c[2]), "+f"(c[3])
                 : "r"(a[0]), "r"(a[1]), "r"(a[2]), "r"(a[3]), "r"(b[0]), "r"(b[1]));
}
__device__ __forceinline__ void ldm_x4(uint32_t* r, uint32_t addr) {
    asm volatile("ldmatrix.sync.aligned.m8n8.x4.shared.b16 {%0,%1,%2,%3}, [%4];"
                 : "=r"(r[0]), "=r"(r[1]), "=r"(r[2]), "=r"(r[3]) : "r"(addr));
}
__device__ __forceinline__ void cp16(uint32_t dst, const void* src) {
    asm volatile("cp.async.cg.shared.global [%0], [%1], 16;" :: "r"(dst), "l"(src));
}
#define CP_COMMIT() asm volatile("cp.async.commit_group;" ::: "memory")
#define CP_WAIT(n)  asm volatile("cp.async.wait_group %0;" :: "n"(n) : "memory")

// ---------------------------------------------------------------------------
// bf16-split GEMM: C[m][n] = sum_k A[m][k]*B[n][k], K=512, fp32 accum.
// C ≈ Ahi·Bhi + Ahi·Blo + Alo·Bhi.
// Block 128x128. BK=32, 3-stage cp.async pipeline (96KB -> 2 CTAs/SM).
// Fill addressing fully hoisted (precomputed per-thread offsets, add-only
// inner loop); stage offsets are compile-time via manual 3-unroll.
// MODE 0: wx for internal nodes.  MODE 1: r-gate -> t.  MODE 2: h_cand.
// MODE 3: U_z GEMM + FUSED combine epilogue (shfl_xor over 4 edge rows).
// MODE 4: leaf GEMM, fused leaf-h epilogue (wh & wz dual tiles).
// ---------------------------------------------------------------------------
#define ROW_B   64
#define TILE_B  (128 * ROW_B)     // 8192
#define STAGE_B (4 * TILE_B)      // 32768
#define SMEM_TOTAL (3 * STAGE_B)  // 98304

template <int MODE>
__global__ __launch_bounds__(256, 2) void mma_gemm(int M, const float* __restrict__ bias,
                                                   int base, int arow0, int ncol0,
                                                   float* __restrict__ hout, int cbase) {
    const bf16* Ahi = (MODE == 0 || MODE == 4) ? g_xhi : (MODE == 1) ? g_hshi
                    : (MODE == 2) ? g_thi : g_hhi;
    const bf16* Alo = (MODE == 0 || MODE == 4) ? g_xlo : (MODE == 1) ? g_hslo
                    : (MODE == 2) ? g_tlo : g_hlo;
    const bf16* Bhi = (MODE == 0 || MODE == 4) ? g_wwhi : (MODE == 1) ? g_urhi
                    : (MODE == 2) ? g_uchi : g_uzhi;
    const bf16* Blo = (MODE == 0 || MODE == 4) ? g_wwlo : (MODE == 1) ? g_urlo
                    : (MODE == 2) ? g_uclo : g_uzlo;

    extern __shared__ __align__(16) char smem[];
    const uint32_t sb = (uint32_t)__cvta_generic_to_shared(smem);
    const int tid = threadIdx.x, lane = tid & 31, warp = tid >> 5;
    const int wm = warp & 3, wn = warp >> 2;          // 4x2 warp grid
    const int bm = blockIdx.y * 128;
    const int bn = blockIdx.x * 128;
    const int bcol0 = (MODE == 4) ? blockIdx.x * 64 : (ncol0 + bn);
    const int qr = lane >> 2;

    const int lrow = lane & 15;                       // fragment source row
    const int lchv = (lane >> 4) & 1;                 // chunk +0/+1
    const int lsel = (lrow >> 1) & 3;                 // swizzle selector

    float acc[2][8][4];
#pragma unroll
    for (int i = 0; i < 2; i++)
#pragma unroll
        for (int j = 0; j < 8; j++)
#pragma unroll
            for (int k = 0; k < 4; k++) acc[i][j][k] = 0.0f;

    const bf16* srcs[4] = {Ahi, Alo, Bhi, Blo};

    // ---- precomputed per-thread fill offsets (kb term added in loop) ----
    uint32_t goff[8];   // byte offset into src tensor
    uint32_t sdst[8];   // smem offset within a stage
#pragma unroll
    for (int t = 0; t < 4; t++) {
#pragma unroll
        for (int j = 0; j < 2; j++) {
            int idx = tid + j * 256;
            int r = idx >> 2, c = idx & 3;
            int grow;
            if (t < 2) grow = arow0 + bm + r;
            else if (MODE == 4) grow = HS + ((r >> 6) & 1) * HS + bcol0 + (r & 63);
            else grow = bcol0 + r;
            goff[t * 2 + j] = (uint32_t)grow * 1024u + (uint32_t)c * 16u;
            sdst[t * 2 + j] = t * TILE_B + r * ROW_B + ((c ^ ((r >> 1) & 3)) << 4);
        }
    }

    auto fill = [&](int sB, int kb) {   // sB = stage byte offset (compile-time)
        const uint32_t kboff = (uint32_t)kb * 64u;
#pragma unroll
        for (int q = 0; q < 8; q++)
            cp16(sb + sB + sdst[q], (const char*)srcs[q >> 1] + goff[q] + kboff);
        CP_COMMIT();
    };

    auto compute = [&](int sB) {
        const uint32_t st = sb + sB;
#pragma unroll
        for (int ks = 0; ks < 2; ks++) {
            const int ch = 2 * ks + lchv;
            uint32_t ah[2][4], al[2][4], bh[4][4], bl[4][4];
#pragma unroll
            for (int mi = 0; mi < 2; mi++) {
                uint32_t ra = st + (wm * 32 + mi * 16 + lrow) * ROW_B + ((ch ^ lsel) << 4);
                ldm_x4(ah[mi], ra);
                ldm_x4(al[mi], ra + TILE_B);
            }
#pragma unroll
            for (int p = 0; p < 4; p++) {
                uint32_t rb = st + 2 * TILE_B + (wn * 64 + p * 16 + lrow) * ROW_B + ((ch ^ lsel) << 4);
                ldm_x4(bh[p], rb);
                ldm_x4(bl[p], rb + TILE_B);
            }
#pragma unroll
            for (int ng = 0; ng < 8; ng++) {
                const int p = ng >> 1, s1 = ng & 1;
                uint32_t bfh[2] = {bh[p][s1], bh[p][s1 + 2]};
                uint32_t bfl[2] = {bl[p][s1], bl[p][s1 + 2]};
#pragma unroll
                for (int mi = 0; mi < 2; mi++) {
                    mma16816(acc[mi][ng], ah[mi], bfh);
                    mma16816(acc[mi][ng], ah[mi], bfl);
                    mma16816(acc[mi][ng], al[mi], bfh);
                }
            }
        }
    };

    fill(0, 0);
    fill(STAGE_B, 1);

    // iterations 0..11 (fill kb+2, wait 2); stages cycle 0,1,2
#pragma unroll 1
    for (int kb = 0; kb < 12; kb += 3) {
        fill(2 * STAGE_B, kb + 2);  CP_WAIT(2); __syncthreads();
        compute(0);                 __syncthreads();
        fill(0, kb + 3);            CP_WAIT(2); __syncthreads();
        compute(STAGE_B);           __syncthreads();
        fill(STAGE_B, kb + 4);      CP_WAIT(2); __syncthreads();
        compute(2 * STAGE_B);       __syncthreads();
    }
    // kb = 12 (fill 14), 13 (fill 15), 14, 15
    fill(2 * STAGE_B, 14); CP_WAIT(2); __syncthreads(); compute(0);           __syncthreads();
    fill(0, 15);           CP_WAIT(2); __syncthreads(); compute(STAGE_B);     __syncthreads();
    CP_WAIT(1);                        __syncthreads(); compute(2 * STAGE_B); __syncthreads();
    CP_WAIT(0);                        __syncthreads(); compute(0);

    // ---------------- epilogues ----------------
    if (MODE == 4) {
        __syncthreads();
        float* sf = (float*)smem;                      // 128 x 65 floats
#pragma unroll
        for (int mi = 0; mi < 2; mi++)
#pragma unroll
            for (int hh = 0; hh < 2; hh++)
#pragma unroll
                for (int ni = 0; ni < 8; ni++) {
                    if (wn == 1) {
                        int row = wm * 32 + mi * 16 + qr + hh * 8;
                        int colw = ni * 8 + (lane & 3) * 2;
                        sf[row * 65 + colw]     = acc[mi][ni][hh * 2 + 0];
                        sf[row * 65 + colw + 1] = acc[mi][ni][hh * 2 + 1];
                    }
                }
        __syncthreads();
        if (wn == 0) {
#pragma unroll
            for (int mi = 0; mi < 2; mi++)
#pragma unroll
                for (int hh = 0; hh < 2; hh++)
#pragma unroll
                    for (int ni = 0; ni < 8; ni++) {
                        int row = wm * 32 + mi * 16 + qr + hh * 8;
                        int colw = ni * 8 + (lane & 3) * 2;
                        int c = bcol0 + colw;
                        float wh0 = acc[mi][ni][hh * 2 + 0] + bias[HS + c];
                        float wh1 = acc[mi][ni][hh * 2 + 1] + bias[HS + c + 1];
                        float wz0 = sf[row * 65 + colw]     + bias[2 * HS + c];
                        float wz1 = sf[row * 65 + colw + 1] + bias[2 * HS + c + 1];
                        float v0 = (1.0f - sigf(wz0)) * tanhf(wh0);
                        float v1 = (1.0f - sigf(wz1)) * tanhf(wh1);
                        size_t node = (size_t)INTERNAL + bm + row;
                        *(float2*)(hout + node * HS + c) = make_float2(v0, v1);
                        bf16 b0 = __float2bfloat16_rn(v0), b1 = __float2bfloat16_rn(v1);
                        *(__nv_bfloat162*)(g_hhi + node * HS + c) = __halves2bfloat162(b0, b1);
                        *(__nv_bfloat162*)(g_hlo + node * HS + c) = __halves2bfloat162(
                            __float2bfloat16_rn(v0 - __bfloat162float(b0)),
                            __float2bfloat16_rn(v1 - __bfloat162float(b1)));
                    }
        }
        return;
    }

    if (MODE == 3) {
        const int Medges = M;
#pragma unroll
        for (int mi = 0; mi < 2; mi++) {
#pragma unroll
            for (int hh = 0; hh < 2; hh++) {
#pragma unroll
                for (int ni = 0; ni < 8; ni++) {
                    int row  = wm * 32 + mi * 16 + qr + hh * 8;
                    int erow = bm + row;                      // within-level edge
                    int col  = bn + wn * 64 + ni * 8 + (lane & 3) * 2;
                    bool ok = (erow < Medges);
                    int node = erow >> 2;
                    float z0 = acc[mi][ni][hh * 2 + 0];
                    float z1 = acc[mi][ni][hh * 2 + 1];
                    float2 hv = make_float2(0.f, 0.f), wz = make_float2(0.f, 0.f);
                    if (ok) {
                        hv = *(const float2*)(hout + (size_t)(cbase + erow) * HS + col);
                        wz = *(const float2*)(g_wx + (size_t)(base + node) * NW + 2 * HS + col);
                    }
                    float p0 = ok ? z0 * hv.x : 0.f;
                    float p1 = ok ? z1 * hv.y : 0.f;
                    float s0 = ok ? sigf(z0 + wz.x) : 0.f;
                    float s1 = ok ? sigf(z1 + wz.y) : 0.f;
                    p0 += __shfl_xor_sync(~0u, p0, 4);  p0 += __shfl_xor_sync(~0u, p0, 8);
                    p1 += __shfl_xor_sync(~0u, p1, 4);  p1 += __shfl_xor_sync(~0u, p1, 8);
                    s0 += __shfl_xor_sync(~0u, s0, 4);  s0 += __shfl_xor_sync(~0u, s0, 8);
                    s1 += __shfl_xor_sync(~0u, s1, 4);  s1 += __shfl_xor_sync(~0u, s1, 8);
                    if (ok && (qr & 3) == 0) {
                        float2 hc = *(const float2*)(g_hcand + (size_t)node * HS + col);
                        float v0 = p0 + (1.0f - s0) * hc.x;
                        float v1 = p1 + (1.0f - s1) * hc.y;
                        *(float2*)(hout + (size_t)(base + node) * HS + col) = make_float2(v0, v1);
                        bf16 b0 = __float2bfloat16_rn(v0), b1 = __float2bfloat16_rn(v1);
                        *(__nv_bfloat162*)(g_hhi + (size_t)(base + node) * HS + col) =
                            __halves2bfloat162(b0, b1);
                        *(__nv_bfloat162*)(g_hlo + (size_t)(base + node) * HS + col) =
                            __halves2bfloat162(
                                __float2bfloat16_rn(v0 - __bfloat162float(b0)),
                                __float2bfloat16_rn(v1 - __bfloat162float(b1)));
                    }
                }
            }
        }
        return;
    }

#pragma unroll
    for (int mi = 0; mi < 2; mi++) {
#pragma unroll
        for (int hh = 0; hh < 2; hh++) {
            int m = bm + wm * 32 + mi * 16 + qr + hh * 8;
            if (m >= M) continue;
#pragma unroll
            for (int ni = 0; ni < 8; ni++) {
                int col = bn + wn * 64 + ni * 8 + (lane & 3) * 2;
                float v0 = acc[mi][ni][hh * 2 + 0];
                float v1 = acc[mi][ni][hh * 2 + 1];
                if (MODE == 0) {
                    float2 bb = *(const float2*)(bias + ncol0 + col);
                    *(float2*)(g_wx + (size_t)(arow0 + m) * NW + ncol0 + col) =
                        make_float2(v0 + bb.x, v1 + bb.y);
                } else if (MODE == 1) {
                    const float2 wr = *(const float2*)(g_wx + (size_t)(base + m) * NW + col);
                    const float2 hs = *(const float2*)(g_hsum + (size_t)m * HS + col);
                    float t0 = sigf(wr.x + v0) * hs.x;
                    float t1 = sigf(wr.y + v1) * hs.y;
                    bf16 h0 = __float2bfloat16_rn(t0), h1 = __float2bfloat16_rn(t1);
                    *(__nv_bfloat162*)(g_thi + (size_t)m * HS + col) = __halves2bfloat162(h0, h1);
                    *(__nv_bfloat162*)(g_tlo + (size_t)m * HS + col) = __halves2bfloat162(
                        __float2bfloat16_rn(t0 - __bfloat162float(h0)),
                        __float2bfloat16_rn(t1 - __bfloat162float(h1)));
                } else if (MODE == 2) {
                    const float2 wh = *(const float2*)(g_wx + (size_t)(base + m) * NW + HS + col);
                    *(float2*)(g_hcand + (size_t)m * HS + col) =
                        make_float2(tanhf(wh.x + v0), tanhf(wh.y + v1));
                }
            }
        }
    }
}

// ---------------- elementwise kernels (vectorized) --------------------------
template <int WHICH>
__global__ void split_f32(const float* __restrict__ in, int n8) {
    int i = blockIdx.x * blockDim.x + threadIdx.x;
    if (i >= n8) return;
    bf16* hi = (WHICH == 0) ? g_xhi : (WHICH == 1) ? g_wwhi
             : (WHICH == 2) ? g_urhi : (WHICH == 3) ? g_uchi : g_uzhi;
    bf16* lo = (WHICH == 0) ? g_xlo : (WHICH == 1) ? g_wwlo
             : (WHICH == 2) ? g_urlo : (WHICH == 3) ? g_uclo : g_uzlo;
    float4 a = ((const float4*)in)[2 * i];
    float4 b = ((const float4*)in)[2 * i + 1];
    float v[8] = {a.x, a.y, a.z, a.w, b.x, b.y, b.z, b.w};
    __nv_bfloat162 hw[4], lw[4];
#pragma unroll
    for (int j = 0; j < 4; j++) {
        bf16 h0 = __float2bfloat16_rn(v[2 * j]);
        bf16 h1 = __float2bfloat16_rn(v[2 * j + 1]);
        hw[j] = __halves2bfloat162(h0, h1);
        lw[j] = __halves2bfloat162(
            __float2bfloat16_rn(v[2 * j] - __bfloat162float(h0)),
            __float2bfloat16_rn(v[2 * j + 1] - __bfloat162float(h1)));
    }
    ((uint4*)hi)[i] = *(uint4*)hw;
    ((uint4*)lo)[i] = *(uint4*)lw;
}

__global__ void child_sum(const float* __restrict__ h, int n4, int cbase) {
    int idx = blockIdx.x * blockDim.x + threadIdx.x;
    if (idx >= n4) return;
    int r = idx >> 7, c4 = idx & 127;
    const float4* hc = (const float4*)(h + (size_t)(cbase + 4 * r) * HS) + c4;
    float4 s0 = hc[0], s1 = hc[128], s2 = hc[256], s3 = hc[384];
    float4 v = make_float4(s0.x + s1.x + s2.x + s3.x, s0.y + s1.y + s2.y + s3.y,
                           s0.z + s1.z + s2.z + s3.z, s0.w + s1.w + s2.w + s3.w);
    ((float4*)g_hsum)[idx] = v;
    float vv[4] = {v.x, v.y, v.z, v.w};
    __nv_bfloat162 hw[2], lw[2];
#pragma unroll
    for (int j = 0; j < 2; j++) {
        bf16 h0 = __float2bfloat16_rn(vv[2 * j]);
        bf16 h1 = __float2bfloat16_rn(vv[2 * j + 1]);
        hw[j] = __halves2bfloat162(h0, h1);
        lw[j] = __halves2bfloat162(
            __float2bfloat16_rn(vv[2 * j] - __bfloat162float(h0)),
            __float2bfloat16_rn(vv[2 * j + 1] - __bfloat162float(h1)));
    }
    ((uint2*)g_hshi)[idx] = *(uint2*)hw;
    ((uint2*)g_hslo)[idx] = *(uint2*)lw;
}

// ---------------------------------------------------------------------------
extern "C" void kernel_launch(void* const* d_in, const int* in_sizes, int n_in,
                              void* d_out, int out_size) {
    const float* x    = (const float*)d_in[0];
    const float* W_w  = (const float*)d_in[1];
    const float* b_w  = (const float*)d_in[2];
    const float* U_r  = (const float*)d_in[3];
    const float* U_hc = (const float*)d_in[4];
    const float* U_z  = (const float*)d_in[5];
    float* h = (float*)d_out;

    static const int S[10] = {0, 1, 5, 21, 85, 341, 1365, 5461, 21845, 87381};

    cudaFuncSetAttribute(mma_gemm<0>, cudaFuncAttributeMaxDynamicSharedMemorySize, SMEM_TOTAL);
    cudaFuncSetAttribute(mma_gemm<1>, cudaFuncAttributeMaxDynamicSharedMemorySize, SMEM_TOTAL);
    cudaFuncSetAttribute(mma_gemm<2>, cudaFuncAttributeMaxDynamicSharedMemorySize, SMEM_TOTAL);
    cudaFuncSetAttribute(mma_gemm<3>, cudaFuncAttributeMaxDynamicSharedMemorySize, SMEM_TOTAL);
    cudaFuncSetAttribute(mma_gemm<4>, cudaFuncAttributeMaxDynamicSharedMemorySize, SMEM_TOTAL);

    // launches 0..2: splits needed by the leaf GEMM
    split_f32<0><<<(N_NODES * HS / 8 + 255) / 256, 256>>>(x, N_NODES * HS / 8);
    split_f32<1><<<(NW * HS / 8 + 255) / 256, 256>>>(W_w, NW * HS / 8);
    split_f32<2><<<(HS * HS / 8 + 255) / 256, 256>>>(U_r, HS * HS / 8);

    // launch index 3 (ncu profiles this): the LEAF GEMM (largest kernel)
    {
        dim3 gl(HS / 64, LEAVES / 128);
        mma_gemm<4><<<gl, 256, SMEM_TOTAL>>>(LEAVES, b_w, 0, INTERNAL, 0, h, 0);
    }

    // internal-node GEMM
    {
        dim3 gi(NW / 128, (INTERNAL + 127) / 128);
        mma_gemm<0><<<gi, 256, SMEM_TOTAL>>>(INTERNAL, b_w, 0, 0, 0, nullptr, 0);
    }

    split_f32<3><<<(HS * HS / 8 + 255) / 256, 256>>>(U_hc, HS * HS / 8);
    split_f32<4><<<(HS * HS / 8 + 255) / 256, 256>>>(U_z, HS * HS / 8);

    // level loop
    for (int l = 1; l <= 8; l++) {
        int d = 8 - l;
        int M = 1 << (2 * d);
        int base = S[d];
        int cbase = S[d + 1];

        child_sum<<<(M * 128 + 255) / 256, 256>>>(h, M * 128, cbase);

        dim3 g1(HS / 128, (M + 127) / 128);
        mma_gemm<1><<<g1, 256, SMEM_TOTAL>>>(M, nullptr, base, 0, 0, nullptr, 0);
        mma_gemm<2><<<g1, 256, SMEM_TOTAL>>>(M, nullptr, base, 0, 0, nullptr, 0);

        // U_z GEMM over 4M edges with fused combine epilogue
        dim3 g3(HS / 128, (4 * M + 127) / 128);
        mma_gemm<3><<<g3, 256, SMEM_TOTAL>>>(4 * M, nullptr, base, cbase, 0, h, cbase);
    }
}